// round 1
// baseline (speedup 1.0000x reference)
#include <cuda_runtime.h>
#include <math.h>

#define BB   2
#define SS   2048
#define DD   1024
#define NH   16
#define HDIM 64
#define NTOK (BB*SS)

// Scratch (device globals: allocation-free per harness rules)
__device__ float g_q[NTOK*DD];    // [b][h][s][d]
__device__ float g_k[NTOK*DD];
__device__ float g_v[NTOK*DD];
__device__ float g_ctx[NTOK*DD];  // [b][s][h*64+d]

// ---------------------------------------------------------------------------
// Shared GEMM tile core: C(128x128) += A[M,K] * W[N,K]^T, K-inner for both.
// 256 threads, BK=16, 8x8 per-thread microtile.
// ---------------------------------------------------------------------------
__device__ __forceinline__ void gemm_tile_core(
    const float* __restrict__ A, const float* __restrict__ W,
    int m0, int n0, int Kdim, float acc[8][8],
    float (*As)[132], float (*Bs)[132])
{
    const int tid = threadIdx.x;
    const int tx = tid & 15, ty = tid >> 4;
    const int lr = tid >> 2;           // 0..63
    const int lc = (tid & 3) * 4;      // 0,4,8,12

    for (int k0 = 0; k0 < Kdim; k0 += 16) {
        #pragma unroll
        for (int p = 0; p < 2; p++) {
            const float4 av = *reinterpret_cast<const float4*>(
                A + (size_t)(m0 + lr + p*64) * Kdim + k0 + lc);
            As[lc+0][lr + p*64] = av.x;
            As[lc+1][lr + p*64] = av.y;
            As[lc+2][lr + p*64] = av.z;
            As[lc+3][lr + p*64] = av.w;
            const float4 bv = *reinterpret_cast<const float4*>(
                W + (size_t)(n0 + lr + p*64) * Kdim + k0 + lc);
            Bs[lc+0][lr + p*64] = bv.x;
            Bs[lc+1][lr + p*64] = bv.y;
            Bs[lc+2][lr + p*64] = bv.z;
            Bs[lc+3][lr + p*64] = bv.w;
        }
        __syncthreads();
        #pragma unroll
        for (int kk = 0; kk < 16; kk++) {
            float a[8], b[8];
            *reinterpret_cast<float4*>(&a[0]) = *reinterpret_cast<const float4*>(&As[kk][ty*8]);
            *reinterpret_cast<float4*>(&a[4]) = *reinterpret_cast<const float4*>(&As[kk][ty*8+4]);
            *reinterpret_cast<float4*>(&b[0]) = *reinterpret_cast<const float4*>(&Bs[kk][tx*8]);
            *reinterpret_cast<float4*>(&b[4]) = *reinterpret_cast<const float4*>(&Bs[kk][tx*8+4]);
            #pragma unroll
            for (int i = 0; i < 8; i++)
                #pragma unroll
                for (int j = 0; j < 8; j++)
                    acc[i][j] = fmaf(a[i], b[j], acc[i][j]);
        }
        __syncthreads();
    }
}

// ---------------------------------------------------------------------------
// Kernel 1: fused QKV projection. grid (8, 32, 3), block 256.
// ---------------------------------------------------------------------------
__global__ __launch_bounds__(256) void qkv_gemm_kernel(
    const float* __restrict__ x,
    const float* __restrict__ Wq,
    const float* __restrict__ Wk,
    const float* __restrict__ Wv)
{
    __shared__ __align__(16) float As[16][132];
    __shared__ __align__(16) float Bs[16][132];

    const float* W   = (blockIdx.z == 0) ? Wq : (blockIdx.z == 1) ? Wk : Wv;
    float*       out = (blockIdx.z == 0) ? g_q : (blockIdx.z == 1) ? g_k : g_v;

    const int m0 = blockIdx.y * 128;
    const int n0 = blockIdx.x * 128;

    float acc[8][8];
    #pragma unroll
    for (int i = 0; i < 8; i++)
        #pragma unroll
        for (int j = 0; j < 8; j++) acc[i][j] = 0.f;

    gemm_tile_core(x, W, m0, n0, DD, acc, As, Bs);

    const int tx = threadIdx.x & 15, ty = threadIdx.x >> 4;
    #pragma unroll
    for (int i = 0; i < 8; i++) {
        const int m = m0 + ty*8 + i;
        const int b = m >> 11;           // /2048
        const int s = m & 2047;
        #pragma unroll
        for (int j = 0; j < 8; j++) {
            const int n = n0 + tx*8 + j;
            const int h = n >> 6;
            const int d = n & 63;
            out[(((size_t)(b*NH + h))*SS + s)*HDIM + d] = acc[i][j];
        }
    }
}

// ---------------------------------------------------------------------------
// Kernel 2: causal flash attention. grid (16 q-tiles, 32 bh), block 256.
// Q tile 128, K/V tile 64, online softmax, P@V through shared.
// smem: Qs[128][65] + KsT[64][65] + Vs[64][65] + Ps[128][65] = 99840 B
// ---------------------------------------------------------------------------
__global__ __launch_bounds__(256) void attn_kernel()
{
    extern __shared__ float sm[];
    float* Qs  = sm;                 // [128][65], row = q, col = d
    float* KsT = Qs  + 128*65;       // [64][65],  row = d, col = key
    float* Vs  = KsT + 64*65;        // [64][65],  row = key, col = d
    float* Ps  = Vs  + 64*65;        // [128][65], row = q, col = key

    const int tid = threadIdx.x;
    const int tx = tid & 15, ty = tid >> 4;
    const int qt = blockIdx.x;
    const int bh = blockIdx.y;

    const float* Qg = g_q + (size_t)bh * SS * HDIM;
    const float* Kg = g_k + (size_t)bh * SS * HDIM;
    const float* Vg = g_v + (size_t)bh * SS * HDIM;
    const int q0 = qt * 128;

    // Load Q tile (128x64)
    #pragma unroll
    for (int r = 0; r < 8; r++) {
        const int idx = tid + r*256;
        const int row = idx >> 4;
        const int c4  = (idx & 15) * 4;
        const float4 qv = *reinterpret_cast<const float4*>(Qg + (size_t)(q0+row)*HDIM + c4);
        Qs[row*65 + c4+0] = qv.x;
        Qs[row*65 + c4+1] = qv.y;
        Qs[row*65 + c4+2] = qv.z;
        Qs[row*65 + c4+3] = qv.w;
    }

    float m_i[8], l_i[8], acc[8][4];
    #pragma unroll
    for (int i = 0; i < 8; i++) {
        m_i[i] = -1e30f; l_i[i] = 0.f;
        #pragma unroll
        for (int j = 0; j < 4; j++) acc[i][j] = 0.f;
    }

    const int ktmax = 2*qt + 1;
    for (int kt = 0; kt <= ktmax; kt++) {
        __syncthreads();   // previous iter's Ps/Vs reads complete
        // Load K (transposed into KsT[d][key]) and V (Vs[key][d])
        #pragma unroll
        for (int r = 0; r < 4; r++) {
            const int idx = tid + r*256;
            const int row = idx >> 4;          // key within tile
            const int c4  = (idx & 15) * 4;    // d
            const float4 kv = *reinterpret_cast<const float4*>(Kg + (size_t)(kt*64+row)*HDIM + c4);
            KsT[(c4+0)*65 + row] = kv.x;
            KsT[(c4+1)*65 + row] = kv.y;
            KsT[(c4+2)*65 + row] = kv.z;
            KsT[(c4+3)*65 + row] = kv.w;
            const float4 vv = *reinterpret_cast<const float4*>(Vg + (size_t)(kt*64+row)*HDIM + c4);
            Vs[row*65 + c4+0] = vv.x;
            Vs[row*65 + c4+1] = vv.y;
            Vs[row*65 + c4+2] = vv.z;
            Vs[row*65 + c4+3] = vv.w;
        }
        __syncthreads();

        // Scores: sc[8][4] = Q(8 rows) . K(4 keys)
        float sc[8][4];
        #pragma unroll
        for (int i = 0; i < 8; i++)
            #pragma unroll
            for (int j = 0; j < 4; j++) sc[i][j] = 0.f;

        #pragma unroll 16
        for (int d = 0; d < 64; d++) {
            float a[8];
            #pragma unroll
            for (int i = 0; i < 8; i++) a[i] = Qs[(ty*8+i)*65 + d];
            float bv[4];
            #pragma unroll
            for (int j = 0; j < 4; j++) bv[j] = KsT[d*65 + tx*4 + j];
            #pragma unroll
            for (int i = 0; i < 8; i++)
                #pragma unroll
                for (int j = 0; j < 4; j++)
                    sc[i][j] = fmaf(a[i], bv[j], sc[i][j]);
        }

        // Scale + causal mask + online softmax update
        #pragma unroll
        for (int i = 0; i < 8; i++) {
            const int qg = q0 + ty*8 + i;
            #pragma unroll
            for (int j = 0; j < 4; j++) {
                float v = sc[i][j] * 0.125f;   // 1/sqrt(64)
                const int kg = kt*64 + tx*4 + j;
                if (kg > qg) v = -1e30f;
                sc[i][j] = v;
            }
            float mx = fmaxf(fmaxf(sc[i][0], sc[i][1]), fmaxf(sc[i][2], sc[i][3]));
            #pragma unroll
            for (int o = 8; o > 0; o >>= 1)
                mx = fmaxf(mx, __shfl_xor_sync(0xffffffffu, mx, o, 16));
            const float mnew = fmaxf(m_i[i], mx);
            const float corr = __expf(m_i[i] - mnew);
            float rs = 0.f;
            #pragma unroll
            for (int j = 0; j < 4; j++) {
                const float p = __expf(sc[i][j] - mnew);
                sc[i][j] = p;
                rs += p;
            }
            #pragma unroll
            for (int o = 8; o > 0; o >>= 1)
                rs += __shfl_xor_sync(0xffffffffu, rs, o, 16);
            l_i[i] = l_i[i]*corr + rs;
            m_i[i] = mnew;
            #pragma unroll
            for (int j = 0; j < 4; j++) acc[i][j] *= corr;
            // stage P
            #pragma unroll
            for (int j = 0; j < 4; j++)
                Ps[(ty*8+i)*65 + tx*4 + j] = sc[i][j];
        }
        __syncthreads();

        // O += P @ V
        #pragma unroll 16
        for (int kk = 0; kk < 64; kk++) {
            float p[8];
            #pragma unroll
            for (int i = 0; i < 8; i++) p[i] = Ps[(ty*8+i)*65 + kk];
            float vv[4];
            #pragma unroll
            for (int j = 0; j < 4; j++) vv[j] = Vs[kk*65 + tx*4 + j];
            #pragma unroll
            for (int i = 0; i < 8; i++)
                #pragma unroll
                for (int j = 0; j < 4; j++)
                    acc[i][j] = fmaf(p[i], vv[j], acc[i][j]);
        }
    }

    // Epilogue: normalize and write ctx [b][s][h*64+d]
    const int b = bh >> 4, h = bh & 15;
    #pragma unroll
    for (int i = 0; i < 8; i++) {
        const float inv = 1.0f / l_i[i];
        const int qg = q0 + ty*8 + i;
        #pragma unroll
        for (int j = 0; j < 4; j++)
            g_ctx[((size_t)(b*SS + qg))*DD + h*HDIM + tx*4 + j] = acc[i][j] * inv;
    }
}

// ---------------------------------------------------------------------------
// Kernel 3: output projection + bias. grid (8, 32), block 256.
// ---------------------------------------------------------------------------
__global__ __launch_bounds__(256) void oproj_kernel(
    const float* __restrict__ Wo,
    const float* __restrict__ bo,
    float* __restrict__ out)
{
    __shared__ __align__(16) float As[16][132];
    __shared__ __align__(16) float Bs[16][132];

    const int m0 = blockIdx.y * 128;
    const int n0 = blockIdx.x * 128;

    float acc[8][8];
    #pragma unroll
    for (int i = 0; i < 8; i++)
        #pragma unroll
        for (int j = 0; j < 8; j++) acc[i][j] = 0.f;

    gemm_tile_core(g_ctx, Wo, m0, n0, DD, acc, As, Bs);

    const int tx = threadIdx.x & 15, ty = threadIdx.x >> 4;
    #pragma unroll
    for (int i = 0; i < 8; i++) {
        const int m = m0 + ty*8 + i;
        #pragma unroll
        for (int j = 0; j < 8; j++) {
            const int n = n0 + tx*8 + j;
            out[(size_t)m*DD + n] = acc[i][j] + bo[n];
        }
    }
}

// ---------------------------------------------------------------------------
// Launch
// ---------------------------------------------------------------------------
extern "C" void kernel_launch(void* const* d_in, const int* in_sizes, int n_in,
                              void* d_out, int out_size)
{
    const float* x  = (const float*)d_in[0];
    const float* Wq = (const float*)d_in[1];
    const float* Wk = (const float*)d_in[2];
    const float* Wv = (const float*)d_in[3];
    const float* Wo = (const float*)d_in[4];
    const float* bo = (const float*)d_in[5];
    float* out = (float*)d_out;

    (void)in_sizes; (void)n_in; (void)out_size;

    // QKV projections
    qkv_gemm_kernel<<<dim3(8, 32, 3), 256>>>(x, Wq, Wk, Wv);

    // Causal flash attention (needs >48KB dynamic smem)
    const int smem_bytes = (128*65 + 64*65 + 64*65 + 128*65) * 4; // 99840
    cudaFuncSetAttribute(attn_kernel, cudaFuncAttributeMaxDynamicSharedMemorySize, smem_bytes);
    attn_kernel<<<dim3(16, 32), 256, smem_bytes>>>();

    // Output projection + bias
    oproj_kernel<<<dim3(8, 32), 256>>>(Wo, bo, out);
}

// round 2
// speedup vs baseline: 2.1543x; 2.1543x over previous
#include <cuda_runtime.h>
#include <math.h>
#include <stdint.h>

#define BB   2
#define SS   2048
#define DD   1024
#define NH   16
#define HDIM 64
#define NTOK (BB*SS)

// Scratch (device globals: allocation-free per harness rules)
__device__ float g_q[NTOK*DD];    // [b][h][s][d]
__device__ float g_k[NTOK*DD];
__device__ float g_v[NTOK*DD];
__device__ float g_ctx[NTOK*DD];  // [b][s][h*64+d]

// ---------------------------------------------------------------------------
// TF32 helpers
// ---------------------------------------------------------------------------
__device__ __forceinline__ uint32_t f2tf(float f) {
    uint32_t u;
    asm("cvt.rna.tf32.f32 %0, %1;" : "=r"(u) : "f"(f));
    return u;
}

__device__ __forceinline__ void mma_tf32(float d[4], const uint32_t a[4],
                                         const uint32_t b[2], const float c[4]) {
    asm volatile(
        "mma.sync.aligned.m16n8k8.row.col.f32.tf32.tf32.f32 "
        "{%0,%1,%2,%3}, {%4,%5,%6,%7}, {%8,%9}, {%10,%11,%12,%13};"
        : "=f"(d[0]), "=f"(d[1]), "=f"(d[2]), "=f"(d[3])
        : "r"(a[0]), "r"(a[1]), "r"(a[2]), "r"(a[3]),
          "r"(b[0]), "r"(b[1]),
          "f"(c[0]), "f"(c[1]), "f"(c[2]), "f"(c[3]));
}

// ---------------------------------------------------------------------------
// GEMM mainloop (tf32 mma): C(128x128) = A[M,K] @ W[N,K]^T.
// 256 threads = 8 warps (2x4), warp tile 64x32, BK=16.
// As/Bs: [k][m|n], stride 136 (conflict-free for frag loads).
// ---------------------------------------------------------------------------
#define GPAD 136

__device__ __forceinline__ void gemm_mma_core(
    const float* __restrict__ A, const float* __restrict__ W,
    int m0, int n0, float acc[4][4][4],
    uint32_t (*As)[GPAD], uint32_t (*Bs)[GPAD])
{
    const int tid  = threadIdx.x;
    const int lane = tid & 31;
    const int warp = tid >> 5;
    const int wm = warp >> 2;        // 0..1
    const int wn = warp & 3;         // 0..3
    const int r  = lane >> 2;        // 0..7
    const int c  = lane & 3;         // 0..3

    const int lr = tid >> 2;         // 0..63
    const int lc = (tid & 3) * 4;    // 0,4,8,12

    // prefetch first K-slice
    float4 pa[2], pb[2];
    #pragma unroll
    for (int p = 0; p < 2; p++) {
        pa[p] = *reinterpret_cast<const float4*>(A + (size_t)(m0 + lr + p*64) * DD + lc);
        pb[p] = *reinterpret_cast<const float4*>(W + (size_t)(n0 + lr + p*64) * DD + lc);
    }

    for (int k0 = 0; k0 < DD; k0 += 16) {
        __syncthreads();   // previous mma reads done
        #pragma unroll
        for (int p = 0; p < 2; p++) {
            As[lc+0][lr + p*64] = f2tf(pa[p].x);
            As[lc+1][lr + p*64] = f2tf(pa[p].y);
            As[lc+2][lr + p*64] = f2tf(pa[p].z);
            As[lc+3][lr + p*64] = f2tf(pa[p].w);
            Bs[lc+0][lr + p*64] = f2tf(pb[p].x);
            Bs[lc+1][lr + p*64] = f2tf(pb[p].y);
            Bs[lc+2][lr + p*64] = f2tf(pb[p].z);
            Bs[lc+3][lr + p*64] = f2tf(pb[p].w);
        }
        __syncthreads();

        if (k0 + 16 < DD) {
            #pragma unroll
            for (int p = 0; p < 2; p++) {
                pa[p] = *reinterpret_cast<const float4*>(A + (size_t)(m0 + lr + p*64) * DD + k0 + 16 + lc);
                pb[p] = *reinterpret_cast<const float4*>(W + (size_t)(n0 + lr + p*64) * DD + k0 + 16 + lc);
            }
        }

        #pragma unroll
        for (int kk = 0; kk < 16; kk += 8) {
            uint32_t af[4][4], bf[4][2];
            #pragma unroll
            for (int mt = 0; mt < 4; mt++) {
                const int mrow = wm*64 + mt*16;
                af[mt][0] = As[kk + c    ][mrow + r    ];
                af[mt][1] = As[kk + c    ][mrow + r + 8];
                af[mt][2] = As[kk + c + 4][mrow + r    ];
                af[mt][3] = As[kk + c + 4][mrow + r + 8];
            }
            #pragma unroll
            for (int nt = 0; nt < 4; nt++) {
                const int ncol = wn*32 + nt*8;
                bf[nt][0] = Bs[kk + c    ][ncol + r];
                bf[nt][1] = Bs[kk + c + 4][ncol + r];
            }
            #pragma unroll
            for (int mt = 0; mt < 4; mt++)
                #pragma unroll
                for (int nt = 0; nt < 4; nt++)
                    mma_tf32(acc[mt][nt], af[mt], bf[nt], acc[mt][nt]);
        }
    }
}

// ---------------------------------------------------------------------------
// Kernel 1: fused QKV projection. grid (8, 32, 3), block 256.
// ---------------------------------------------------------------------------
__global__ __launch_bounds__(256) void qkv_gemm_kernel(
    const float* __restrict__ x,
    const float* __restrict__ Wq,
    const float* __restrict__ Wk,
    const float* __restrict__ Wv)
{
    __shared__ __align__(16) uint32_t As[16][GPAD];
    __shared__ __align__(16) uint32_t Bs[16][GPAD];

    const float* W   = (blockIdx.z == 0) ? Wq : (blockIdx.z == 1) ? Wk : Wv;
    float*       out = (blockIdx.z == 0) ? g_q : (blockIdx.z == 1) ? g_k : g_v;

    const int m0 = blockIdx.y * 128;
    const int n0 = blockIdx.x * 128;

    float acc[4][4][4];
    #pragma unroll
    for (int i = 0; i < 4; i++)
        #pragma unroll
        for (int j = 0; j < 4; j++)
            #pragma unroll
            for (int k = 0; k < 4; k++) acc[i][j][k] = 0.f;

    gemm_mma_core(x, W, m0, n0, acc, As, Bs);

    const int lane = threadIdx.x & 31;
    const int warp = threadIdx.x >> 5;
    const int wm = warp >> 2, wn = warp & 3;
    const int r = lane >> 2, c = lane & 3;

    #pragma unroll
    for (int mt = 0; mt < 4; mt++) {
        #pragma unroll
        for (int nt = 0; nt < 4; nt++) {
            #pragma unroll
            for (int half = 0; half < 2; half++) {
                const int m = m0 + wm*64 + mt*16 + r + half*8;
                const int b = m >> 11;
                const int s = m & 2047;
                const int n = n0 + wn*32 + nt*8 + c*2;
                const int h = n >> 6;
                const int d = n & 63;
                float* o = out + (((size_t)(b*NH + h))*SS + s)*HDIM + d;
                o[0] = acc[mt][nt][half*2 + 0];
                o[1] = acc[mt][nt][half*2 + 1];
            }
        }
    }
}

// ---------------------------------------------------------------------------
// Kernel 2: causal flash attention, tf32 mma.
// grid (16 q-tiles, 32 bh), block 256 (8 warps, 16 q-rows per warp).
// smem: KsT[64][72] + Vs[64][72] + Ps[128][68]  (tf32 bits) = 71680 B
// ---------------------------------------------------------------------------
#define KVPAD 72
#define PPAD  68

__global__ __launch_bounds__(256) void attn_kernel()
{
    extern __shared__ uint32_t sm[];
    uint32_t (*KsT)[KVPAD] = reinterpret_cast<uint32_t (*)[KVPAD]>(sm);                 // [d][key]
    uint32_t (*Vs)[KVPAD]  = reinterpret_cast<uint32_t (*)[KVPAD]>(sm + 64*KVPAD);      // [key][d]
    uint32_t (*Ps)[PPAD]   = reinterpret_cast<uint32_t (*)[PPAD]> (sm + 2*64*KVPAD);    // [q][key]

    const int tid  = threadIdx.x;
    const int lane = tid & 31;
    const int warp = tid >> 5;
    const int r = lane >> 2;     // 0..7
    const int c = lane & 3;      // 0..3
    const int qt = blockIdx.x;
    const int bh = blockIdx.y;

    const float* Qg = g_q + (size_t)bh * SS * HDIM;
    const float* Kg = g_k + (size_t)bh * SS * HDIM;
    const float* Vg = g_v + (size_t)bh * SS * HDIM;
    const int q0 = qt * 128;
    const int qbase = q0 + warp * 16;

    // Q fragments (register-resident, pre-scaled by 1/sqrt(64))
    uint32_t qf[8][4];
    #pragma unroll
    for (int kk = 0; kk < 8; kk++) {
        qf[kk][0] = f2tf(0.125f * Qg[(size_t)(qbase + r    )*HDIM + kk*8 + c    ]);
        qf[kk][1] = f2tf(0.125f * Qg[(size_t)(qbase + r + 8)*HDIM + kk*8 + c    ]);
        qf[kk][2] = f2tf(0.125f * Qg[(size_t)(qbase + r    )*HDIM + kk*8 + c + 4]);
        qf[kk][3] = f2tf(0.125f * Qg[(size_t)(qbase + r + 8)*HDIM + kk*8 + c + 4]);
    }

    float of[8][4];
    #pragma unroll
    for (int nt = 0; nt < 8; nt++)
        #pragma unroll
        for (int j = 0; j < 4; j++) of[nt][j] = 0.f;
    float m0i = -1e30f, m1i = -1e30f, l0i = 0.f, l1i = 0.f;

    const int ktmax = 2*qt + 1;
    for (int kt = 0; kt <= ktmax; kt++) {
        __syncthreads();   // protect KsT/Vs from previous iteration's readers
        // cooperative K/V tile load (64x64 each), cvt to tf32
        #pragma unroll
        for (int rr = 0; rr < 4; rr++) {
            const int idx = tid + rr*256;
            const int row = idx >> 4;
            const int c4  = (idx & 15) * 4;
            const float4 kv = *reinterpret_cast<const float4*>(Kg + (size_t)(kt*64+row)*HDIM + c4);
            KsT[c4+0][row] = f2tf(kv.x);
            KsT[c4+1][row] = f2tf(kv.y);
            KsT[c4+2][row] = f2tf(kv.z);
            KsT[c4+3][row] = f2tf(kv.w);
            const float4 vv = *reinterpret_cast<const float4*>(Vg + (size_t)(kt*64+row)*HDIM + c4);
            Vs[row][c4+0] = f2tf(vv.x);
            Vs[row][c4+1] = f2tf(vv.y);
            Vs[row][c4+2] = f2tf(vv.z);
            Vs[row][c4+3] = f2tf(vv.w);
        }
        __syncthreads();

        // causal early-exit: this warp's rows all precede the key tile
        if (kt*64 > qbase + 15) continue;

        // S = Q @ K^T   (m16 x n64), fragments sf[nt][4]
        float sf[8][4];
        #pragma unroll
        for (int nt = 0; nt < 8; nt++)
            #pragma unroll
            for (int j = 0; j < 4; j++) sf[nt][j] = 0.f;

        #pragma unroll
        for (int kk = 0; kk < 8; kk++) {
            #pragma unroll
            for (int nt = 0; nt < 8; nt++) {
                uint32_t bf[2];
                bf[0] = KsT[kk*8 + c    ][nt*8 + r];
                bf[1] = KsT[kk*8 + c + 4][nt*8 + r];
                mma_tf32(sf[nt], qf[kk], bf, sf[nt]);
            }
        }

        // causal mask
        const int qg0 = qbase + r;
        const int qg1 = qg0 + 8;
        #pragma unroll
        for (int nt = 0; nt < 8; nt++) {
            const int col0 = kt*64 + nt*8 + c*2;
            if (col0     > qg0) sf[nt][0] = -1e30f;
            if (col0 + 1 > qg0) sf[nt][1] = -1e30f;
            if (col0     > qg1) sf[nt][2] = -1e30f;
            if (col0 + 1 > qg1) sf[nt][3] = -1e30f;
        }

        // row max (per thread, then quad shuffle over lane%4)
        float mx0 = -1e30f, mx1 = -1e30f;
        #pragma unroll
        for (int nt = 0; nt < 8; nt++) {
            mx0 = fmaxf(mx0, fmaxf(sf[nt][0], sf[nt][1]));
            mx1 = fmaxf(mx1, fmaxf(sf[nt][2], sf[nt][3]));
        }
        mx0 = fmaxf(mx0, __shfl_xor_sync(0xffffffffu, mx0, 1));
        mx0 = fmaxf(mx0, __shfl_xor_sync(0xffffffffu, mx0, 2));
        mx1 = fmaxf(mx1, __shfl_xor_sync(0xffffffffu, mx1, 1));
        mx1 = fmaxf(mx1, __shfl_xor_sync(0xffffffffu, mx1, 2));

        const float mn0 = fmaxf(m0i, mx0);
        const float mn1 = fmaxf(m1i, mx1);
        const float cor0 = __expf(m0i - mn0);
        const float cor1 = __expf(m1i - mn1);

        float s0 = 0.f, s1 = 0.f;
        #pragma unroll
        for (int nt = 0; nt < 8; nt++) {
            const float p00 = __expf(sf[nt][0] - mn0);
            const float p01 = __expf(sf[nt][1] - mn0);
            const float p10 = __expf(sf[nt][2] - mn1);
            const float p11 = __expf(sf[nt][3] - mn1);
            s0 += p00 + p01;
            s1 += p10 + p11;
            const int kc = nt*8 + c*2;
            Ps[warp*16 + r    ][kc    ] = f2tf(p00);
            Ps[warp*16 + r    ][kc + 1] = f2tf(p01);
            Ps[warp*16 + r + 8][kc    ] = f2tf(p10);
            Ps[warp*16 + r + 8][kc + 1] = f2tf(p11);
        }
        s0 += __shfl_xor_sync(0xffffffffu, s0, 1);
        s0 += __shfl_xor_sync(0xffffffffu, s0, 2);
        s1 += __shfl_xor_sync(0xffffffffu, s1, 1);
        s1 += __shfl_xor_sync(0xffffffffu, s1, 2);

        l0i = l0i * cor0 + s0;
        l1i = l1i * cor1 + s1;
        m0i = mn0;
        m1i = mn1;

        #pragma unroll
        for (int nt = 0; nt < 8; nt++) {
            of[nt][0] *= cor0;
            of[nt][1] *= cor0;
            of[nt][2] *= cor1;
            of[nt][3] *= cor1;
        }

        __syncwarp();   // Ps is per-warp private: warp-scope visibility suffices

        // O += P @ V
        #pragma unroll
        for (int kk = 0; kk < 8; kk++) {
            uint32_t af[4];
            af[0] = Ps[warp*16 + r    ][kk*8 + c    ];
            af[1] = Ps[warp*16 + r + 8][kk*8 + c    ];
            af[2] = Ps[warp*16 + r    ][kk*8 + c + 4];
            af[3] = Ps[warp*16 + r + 8][kk*8 + c + 4];
            #pragma unroll
            for (int nt = 0; nt < 8; nt++) {
                uint32_t bf[2];
                bf[0] = Vs[kk*8 + c    ][nt*8 + r];
                bf[1] = Vs[kk*8 + c + 4][nt*8 + r];
                mma_tf32(of[nt], af, bf, of[nt]);
            }
        }
    }

    // epilogue: normalize, write ctx [b][s][h*64+d]
    const int b = bh >> 4, h = bh & 15;
    const float inv0 = 1.0f / l0i;
    const float inv1 = 1.0f / l1i;
    const int qg0 = qbase + r;
    #pragma unroll
    for (int nt = 0; nt < 8; nt++) {
        const int d = nt*8 + c*2;
        float* o0 = g_ctx + ((size_t)(b*SS + qg0    ))*DD + h*HDIM + d;
        float* o1 = g_ctx + ((size_t)(b*SS + qg0 + 8))*DD + h*HDIM + d;
        o0[0] = of[nt][0] * inv0;
        o0[1] = of[nt][1] * inv0;
        o1[0] = of[nt][2] * inv1;
        o1[1] = of[nt][3] * inv1;
    }
}

// ---------------------------------------------------------------------------
// Kernel 3: output projection + bias. grid (8, 32), block 256.
// ---------------------------------------------------------------------------
__global__ __launch_bounds__(256) void oproj_kernel(
    const float* __restrict__ Wo,
    const float* __restrict__ bo,
    float* __restrict__ out)
{
    __shared__ __align__(16) uint32_t As[16][GPAD];
    __shared__ __align__(16) uint32_t Bs[16][GPAD];

    const int m0 = blockIdx.y * 128;
    const int n0 = blockIdx.x * 128;

    float acc[4][4][4];
    #pragma unroll
    for (int i = 0; i < 4; i++)
        #pragma unroll
        for (int j = 0; j < 4; j++)
            #pragma unroll
            for (int k = 0; k < 4; k++) acc[i][j][k] = 0.f;

    gemm_mma_core(g_ctx, Wo, m0, n0, acc, As, Bs);

    const int lane = threadIdx.x & 31;
    const int warp = threadIdx.x >> 5;
    const int wm = warp >> 2, wn = warp & 3;
    const int r = lane >> 2, c = lane & 3;

    #pragma unroll
    for (int mt = 0; mt < 4; mt++) {
        #pragma unroll
        for (int nt = 0; nt < 4; nt++) {
            #pragma unroll
            for (int half = 0; half < 2; half++) {
                const int m = m0 + wm*64 + mt*16 + r + half*8;
                const int n = n0 + wn*32 + nt*8 + c*2;
                float* o = out + (size_t)m*DD + n;
                o[0] = acc[mt][nt][half*2 + 0] + bo[n];
                o[1] = acc[mt][nt][half*2 + 1] + bo[n + 1];
            }
        }
    }
}

// ---------------------------------------------------------------------------
// Launch
// ---------------------------------------------------------------------------
extern "C" void kernel_launch(void* const* d_in, const int* in_sizes, int n_in,
                              void* d_out, int out_size)
{
    const float* x  = (const float*)d_in[0];
    const float* Wq = (const float*)d_in[1];
    const float* Wk = (const float*)d_in[2];
    const float* Wv = (const float*)d_in[3];
    const float* Wo = (const float*)d_in[4];
    const float* bo = (const float*)d_in[5];
    float* out = (float*)d_out;

    (void)in_sizes; (void)n_in; (void)out_size;

    qkv_gemm_kernel<<<dim3(8, 32, 3), 256>>>(x, Wq, Wk, Wv);

    const int smem_bytes = (2*64*KVPAD + 128*PPAD) * 4;   // 71680
    cudaFuncSetAttribute(attn_kernel, cudaFuncAttributeMaxDynamicSharedMemorySize, smem_bytes);
    attn_kernel<<<dim3(16, 32), 256, smem_bytes>>>();

    oproj_kernel<<<dim3(8, 32), 256>>>(Wo, bo, out);
}

// round 4
// speedup vs baseline: 2.4558x; 1.1400x over previous
#include <cuda_runtime.h>
#include <math.h>
#include <stdint.h>

#define BB   2
#define SS   2048
#define DD   1024
#define NH   16
#define HDIM 64
#define NTOK (BB*SS)

// Scratch (device globals: allocation-free per harness rules)
__device__ float g_q[NTOK*DD];    // [b][h][s][d]
__device__ float g_k[NTOK*DD];
__device__ float g_v[NTOK*DD];
__device__ float g_ctx[NTOK*DD];  // [b][s][h*64+d]

// ---------------------------------------------------------------------------
// Helpers
// ---------------------------------------------------------------------------
__device__ __forceinline__ uint32_t smem_u32(const void* p) {
    uint32_t a;
    asm("{ .reg .u64 t; cvta.to.shared.u64 t, %1; cvt.u32.u64 %0, t; }"
        : "=r"(a) : "l"(p));
    return a;
}
__device__ __forceinline__ uint32_t f2tf(float f) {
    uint32_t u;
    asm("cvt.rna.tf32.f32 %0, %1;" : "=r"(u) : "f"(f));
    return u;
}
__device__ __forceinline__ void mma_tf32(float d[4], const uint32_t a[4],
                                         const uint32_t* b, const float c[4]) {
    asm volatile(
        "mma.sync.aligned.m16n8k8.row.col.f32.tf32.tf32.f32 "
        "{%0,%1,%2,%3}, {%4,%5,%6,%7}, {%8,%9}, {%10,%11,%12,%13};"
        : "=f"(d[0]), "=f"(d[1]), "=f"(d[2]), "=f"(d[3])
        : "r"(a[0]), "r"(a[1]), "r"(a[2]), "r"(a[3]),
          "r"(b[0]), "r"(b[1]),
          "f"(c[0]), "f"(c[1]), "f"(c[2]), "f"(c[3]));
}
__device__ __forceinline__ void lds128(uint32_t r[4], uint32_t addr) {
    asm volatile("ld.shared.v4.b32 {%0,%1,%2,%3}, [%4];"
        : "=r"(r[0]), "=r"(r[1]), "=r"(r[2]), "=r"(r[3]) : "r"(addr));
}
__device__ __forceinline__ void sts32(uint32_t addr, uint32_t v) {
    asm volatile("st.shared.b32 [%0], %1;" :: "r"(addr), "r"(v) : "memory");
}

// ---------------------------------------------------------------------------
// Fragment-packed GEMM: C(128x128) = A[m0:+128, :] @ W[n0:+128, :]^T, K=1024.
// 256 threads = 8 warps (2x4), warp tile 64x32, BK=32, double-buffered smem.
//
// Smem fragment layouts (per buffer):
//  A: [kstep(4)][tile16(8)][lane(32)][reg(4)] u32, kstep stride 4112B (16B pad)
//     value A[row][k]: tile16=row>>4, hi=(row>>3)&1, rr=row&7,
//                      kstep=k>>3, khalf=(k>>2)&1, cc=k&3
//     lane=rr*4+cc, reg=hi+2*khalf  -> mma A frag = one LDS.128
//  B: [ksteppair(2)][ntile(16)][lane(32)][reg(4)] u32, ksp stride 8208B
//     value W[n][k]: ntile=n>>3, rr=n&7, ksp=k>>4, ko=(k>>3)&1,
//                    khalf=(k>>2)&1, cc=k&3
//     lane=rr*4+cc, reg=khalf+2*ko  -> B frags for 2 ksteps = one LDS.128
// ---------------------------------------------------------------------------
#define AKS   4112u                  // A kstep block stride (bytes)
#define BKS   8208u                  // B ksteppair block stride (bytes)
#define AOFF  0u
#define BOFF  (4u*AKS)               // 16448
#define BUFST (BOFF + 2u*BKS)        // 32864
#define SMEM_GEMM (2*BUFST)          // 65728 bytes

__device__ __forceinline__ void stage_chunk(
    uint32_t sb, const float4 pa[4], const float4 pb[4],
    int lrow, int lci)
{
    const int kstep = lci >> 1;
    const int khalf = lci & 1;
    const int ksp   = lci >> 2;
    const int ko    = (lci >> 1) & 1;
    #pragma unroll
    for (int p = 0; p < 4; p++) {
        const int row = lrow + p * 32;
        // A
        {
            const int tile16 = row >> 4, hi = (row >> 3) & 1, rr = row & 7;
            const uint32_t ad = sb + AOFF + kstep*AKS +
                                (uint32_t)(tile16*512 + rr*64 + hi*4 + khalf*8);
            sts32(ad,      f2tf(pa[p].x));
            sts32(ad + 16, f2tf(pa[p].y));
            sts32(ad + 32, f2tf(pa[p].z));
            sts32(ad + 48, f2tf(pa[p].w));
        }
        // B
        {
            const int ntile = row >> 3, rr = row & 7;
            const uint32_t bd = sb + BOFF + ksp*BKS +
                                (uint32_t)(ntile*512 + rr*64 + khalf*4 + ko*8);
            sts32(bd,      f2tf(pb[p].x));
            sts32(bd + 16, f2tf(pb[p].y));
            sts32(bd + 32, f2tf(pb[p].z));
            sts32(bd + 48, f2tf(pb[p].w));
        }
    }
}

__device__ __forceinline__ void tc_gemm_core(
    const float* __restrict__ A, const float* __restrict__ W,
    int m0, int n0, uint32_t sbase, float acc[4][4][4])
{
    const int tid  = threadIdx.x;
    const int lane = tid & 31;
    const int warp = tid >> 5;
    const int wm = warp >> 2;            // 0..1
    const int wn = warp & 3;             // 0..3
    const int lrow = tid >> 3;           // 0..31
    const int lci  = tid & 7;            // 16B chunk of 128B k-row

    const uint32_t a_rd = sbase + AOFF + (uint32_t)((wm*4)*512 + lane*16);
    const uint32_t b_rd = sbase + BOFF + (uint32_t)((wn*4)*512 + lane*16);

    // prefetch chunk 0
    float4 pa[4], pb[4];
    #pragma unroll
    for (int p = 0; p < 4; p++) {
        pa[p] = *reinterpret_cast<const float4*>(A + (size_t)(m0 + lrow + p*32)*DD + lci*4);
        pb[p] = *reinterpret_cast<const float4*>(W + (size_t)(n0 + lrow + p*32)*DD + lci*4);
    }
    stage_chunk(sbase, pa, pb, lrow, lci);
    __syncthreads();

    for (int i = 0; i < 32; i++) {
        const uint32_t bufo = (uint32_t)(i & 1) * BUFST;
        // prefetch next chunk (LDG in flight during mma phase)
        if (i + 1 < 32) {
            const int k0 = (i + 1) * 32;
            #pragma unroll
            for (int p = 0; p < 4; p++) {
                pa[p] = *reinterpret_cast<const float4*>(A + (size_t)(m0 + lrow + p*32)*DD + k0 + lci*4);
                pb[p] = *reinterpret_cast<const float4*>(W + (size_t)(n0 + lrow + p*32)*DD + k0 + lci*4);
            }
        }

        // compute 4 ksteps from current buffer
        uint32_t bp[4][4];
        #pragma unroll
        for (int ks = 0; ks < 4; ks++) {
            uint32_t af[4][4];
            #pragma unroll
            for (int mt = 0; mt < 4; mt++)
                lds128(af[mt], a_rd + bufo + (uint32_t)ks*AKS + (uint32_t)(mt*512));
            if ((ks & 1) == 0) {
                #pragma unroll
                for (int nt = 0; nt < 4; nt++)
                    lds128(bp[nt], b_rd + bufo + (uint32_t)(ks>>1)*BKS + (uint32_t)(nt*512));
            }
            #pragma unroll
            for (int mt = 0; mt < 4; mt++)
                #pragma unroll
                for (int nt = 0; nt < 4; nt++)
                    mma_tf32(acc[mt][nt], af[mt],
                             (ks & 1) ? &bp[nt][2] : &bp[nt][0], acc[mt][nt]);
        }

        // stage next chunk into the other buffer
        if (i + 1 < 32)
            stage_chunk(sbase + (BUFST - bufo), pa, pb, lrow, lci);
        __syncthreads();
    }
}

// ---------------------------------------------------------------------------
// Kernel 1: fused QKV projection. grid (8, 32, 3), block 256.
// ---------------------------------------------------------------------------
__global__ __launch_bounds__(256) void qkv_gemm_kernel(
    const float* __restrict__ x,
    const float* __restrict__ Wq,
    const float* __restrict__ Wk,
    const float* __restrict__ Wv)
{
    extern __shared__ char smx[];
    const uint32_t sbase = smem_u32(smx);

    const float* W   = (blockIdx.z == 0) ? Wq : (blockIdx.z == 1) ? Wk : Wv;
    float*       out = (blockIdx.z == 0) ? g_q : (blockIdx.z == 1) ? g_k : g_v;

    const int m0 = blockIdx.y * 128;
    const int n0 = blockIdx.x * 128;

    float acc[4][4][4];
    #pragma unroll
    for (int i = 0; i < 4; i++)
        #pragma unroll
        for (int j = 0; j < 4; j++)
            #pragma unroll
            for (int k = 0; k < 4; k++) acc[i][j][k] = 0.f;

    tc_gemm_core(x, W, m0, n0, sbase, acc);

    const int lane = threadIdx.x & 31;
    const int warp = threadIdx.x >> 5;
    const int wm = warp >> 2, wn = warp & 3;
    const int r = lane >> 2, c = lane & 3;

    #pragma unroll
    for (int mt = 0; mt < 4; mt++) {
        #pragma unroll
        for (int nt = 0; nt < 4; nt++) {
            #pragma unroll
            for (int half = 0; half < 2; half++) {
                const int m = m0 + wm*64 + mt*16 + r + half*8;
                const int b = m >> 11;
                const int s = m & 2047;
                const int n = n0 + wn*32 + nt*8 + c*2;
                const int h = n >> 6;
                const int d = n & 63;
                float* o = out + (((size_t)(b*NH + h))*SS + s)*HDIM + d;
                o[0] = acc[mt][nt][half*2 + 0];
                o[1] = acc[mt][nt][half*2 + 1];
            }
        }
    }
}

// ---------------------------------------------------------------------------
// Kernel 3: output projection + bias. grid (8, 32), block 256.
// ---------------------------------------------------------------------------
__global__ __launch_bounds__(256) void oproj_kernel(
    const float* __restrict__ Wo,
    const float* __restrict__ bo,
    float* __restrict__ out)
{
    extern __shared__ char smx[];
    const uint32_t sbase = smem_u32(smx);

    const int m0 = blockIdx.y * 128;
    const int n0 = blockIdx.x * 128;

    float acc[4][4][4];
    #pragma unroll
    for (int i = 0; i < 4; i++)
        #pragma unroll
        for (int j = 0; j < 4; j++)
            #pragma unroll
            for (int k = 0; k < 4; k++) acc[i][j][k] = 0.f;

    tc_gemm_core(g_ctx, Wo, m0, n0, sbase, acc);

    const int lane = threadIdx.x & 31;
    const int warp = threadIdx.x >> 5;
    const int wm = warp >> 2, wn = warp & 3;
    const int r = lane >> 2, c = lane & 3;

    #pragma unroll
    for (int mt = 0; mt < 4; mt++) {
        #pragma unroll
        for (int nt = 0; nt < 4; nt++) {
            #pragma unroll
            for (int half = 0; half < 2; half++) {
                const int m = m0 + wm*64 + mt*16 + r + half*8;
                const int n = n0 + wn*32 + nt*8 + c*2;
                float* o = out + (size_t)m*DD + n;
                o[0] = acc[mt][nt][half*2 + 0] + bo[n];
                o[1] = acc[mt][nt][half*2 + 1] + bo[n + 1];
            }
        }
    }
}

// ---------------------------------------------------------------------------
// Kernel 2: causal flash attention (unchanged from round 2 — passing).
// ---------------------------------------------------------------------------
#define KVPAD 72
#define PPAD  68

__global__ __launch_bounds__(256) void attn_kernel()
{
    extern __shared__ uint32_t sm[];
    uint32_t (*KsT)[KVPAD] = reinterpret_cast<uint32_t (*)[KVPAD]>(sm);
    uint32_t (*Vs)[KVPAD]  = reinterpret_cast<uint32_t (*)[KVPAD]>(sm + 64*KVPAD);
    uint32_t (*Ps)[PPAD]   = reinterpret_cast<uint32_t (*)[PPAD]> (sm + 2*64*KVPAD);

    const int tid  = threadIdx.x;
    const int lane = tid & 31;
    const int warp = tid >> 5;
    const int r = lane >> 2;
    const int c = lane & 3;
    const int qt = blockIdx.x;
    const int bh = blockIdx.y;

    const float* Qg = g_q + (size_t)bh * SS * HDIM;
    const float* Kg = g_k + (size_t)bh * SS * HDIM;
    const float* Vg = g_v + (size_t)bh * SS * HDIM;
    const int q0 = qt * 128;
    const int qbase = q0 + warp * 16;

    uint32_t qf[8][4];
    #pragma unroll
    for (int kk = 0; kk < 8; kk++) {
        qf[kk][0] = f2tf(0.125f * Qg[(size_t)(qbase + r    )*HDIM + kk*8 + c    ]);
        qf[kk][1] = f2tf(0.125f * Qg[(size_t)(qbase + r + 8)*HDIM + kk*8 + c    ]);
        qf[kk][2] = f2tf(0.125f * Qg[(size_t)(qbase + r    )*HDIM + kk*8 + c + 4]);
        qf[kk][3] = f2tf(0.125f * Qg[(size_t)(qbase + r + 8)*HDIM + kk*8 + c + 4]);
    }

    float of[8][4];
    #pragma unroll
    for (int nt = 0; nt < 8; nt++)
        #pragma unroll
        for (int j = 0; j < 4; j++) of[nt][j] = 0.f;
    float m0i = -1e30f, m1i = -1e30f, l0i = 0.f, l1i = 0.f;

    const int ktmax = 2*qt + 1;
    for (int kt = 0; kt <= ktmax; kt++) {
        __syncthreads();
        #pragma unroll
        for (int rr = 0; rr < 4; rr++) {
            const int idx = tid + rr*256;
            const int row = idx >> 4;
            const int c4  = (idx & 15) * 4;
            const float4 kv = *reinterpret_cast<const float4*>(Kg + (size_t)(kt*64+row)*HDIM + c4);
            KsT[c4+0][row] = f2tf(kv.x);
            KsT[c4+1][row] = f2tf(kv.y);
            KsT[c4+2][row] = f2tf(kv.z);
            KsT[c4+3][row] = f2tf(kv.w);
            const float4 vv = *reinterpret_cast<const float4*>(Vg + (size_t)(kt*64+row)*HDIM + c4);
            Vs[row][c4+0] = f2tf(vv.x);
            Vs[row][c4+1] = f2tf(vv.y);
            Vs[row][c4+2] = f2tf(vv.z);
            Vs[row][c4+3] = f2tf(vv.w);
        }
        __syncthreads();

        if (kt*64 > qbase + 15) continue;

        float sf[8][4];
        #pragma unroll
        for (int nt = 0; nt < 8; nt++)
            #pragma unroll
            for (int j = 0; j < 4; j++) sf[nt][j] = 0.f;

        #pragma unroll
        for (int kk = 0; kk < 8; kk++) {
            #pragma unroll
            for (int nt = 0; nt < 8; nt++) {
                uint32_t bf[2];
                bf[0] = KsT[kk*8 + c    ][nt*8 + r];
                bf[1] = KsT[kk*8 + c + 4][nt*8 + r];
                mma_tf32(sf[nt], qf[kk], bf, sf[nt]);
            }
        }

        const int qg0 = qbase + r;
        const int qg1 = qg0 + 8;
        #pragma unroll
        for (int nt = 0; nt < 8; nt++) {
            const int col0 = kt*64 + nt*8 + c*2;
            if (col0     > qg0) sf[nt][0] = -1e30f;
            if (col0 + 1 > qg0) sf[nt][1] = -1e30f;
            if (col0     > qg1) sf[nt][2] = -1e30f;
            if (col0 + 1 > qg1) sf[nt][3] = -1e30f;
        }

        float mx0 = -1e30f, mx1 = -1e30f;
        #pragma unroll
        for (int nt = 0; nt < 8; nt++) {
            mx0 = fmaxf(mx0, fmaxf(sf[nt][0], sf[nt][1]));
            mx1 = fmaxf(mx1, fmaxf(sf[nt][2], sf[nt][3]));
        }
        mx0 = fmaxf(mx0, __shfl_xor_sync(0xffffffffu, mx0, 1));
        mx0 = fmaxf(mx0, __shfl_xor_sync(0xffffffffu, mx0, 2));
        mx1 = fmaxf(mx1, __shfl_xor_sync(0xffffffffu, mx1, 1));
        mx1 = fmaxf(mx1, __shfl_xor_sync(0xffffffffu, mx1, 2));

        const float mn0 = fmaxf(m0i, mx0);
        const float mn1 = fmaxf(m1i, mx1);
        const float cor0 = __expf(m0i - mn0);
        const float cor1 = __expf(m1i - mn1);

        float s0 = 0.f, s1 = 0.f;
        #pragma unroll
        for (int nt = 0; nt < 8; nt++) {
            const float p00 = __expf(sf[nt][0] - mn0);
            const float p01 = __expf(sf[nt][1] - mn0);
            const float p10 = __expf(sf[nt][2] - mn1);
            const float p11 = __expf(sf[nt][3] - mn1);
            s0 += p00 + p01;
            s1 += p10 + p11;
            const int kc = nt*8 + c*2;
            Ps[warp*16 + r    ][kc    ] = f2tf(p00);
            Ps[warp*16 + r    ][kc + 1] = f2tf(p01);
            Ps[warp*16 + r + 8][kc    ] = f2tf(p10);
            Ps[warp*16 + r + 8][kc + 1] = f2tf(p11);
        }
        s0 += __shfl_xor_sync(0xffffffffu, s0, 1);
        s0 += __shfl_xor_sync(0xffffffffu, s0, 2);
        s1 += __shfl_xor_sync(0xffffffffu, s1, 1);
        s1 += __shfl_xor_sync(0xffffffffu, s1, 2);

        l0i = l0i * cor0 + s0;
        l1i = l1i * cor1 + s1;
        m0i = mn0;
        m1i = mn1;

        #pragma unroll
        for (int nt = 0; nt < 8; nt++) {
            of[nt][0] *= cor0;
            of[nt][1] *= cor0;
            of[nt][2] *= cor1;
            of[nt][3] *= cor1;
        }

        __syncwarp();

        #pragma unroll
        for (int kk = 0; kk < 8; kk++) {
            uint32_t af[4];
            af[0] = Ps[warp*16 + r    ][kk*8 + c    ];
            af[1] = Ps[warp*16 + r + 8][kk*8 + c    ];
            af[2] = Ps[warp*16 + r    ][kk*8 + c + 4];
            af[3] = Ps[warp*16 + r + 8][kk*8 + c + 4];
            #pragma unroll
            for (int nt = 0; nt < 8; nt++) {
                uint32_t bf[2];
                bf[0] = Vs[kk*8 + c    ][nt*8 + r];
                bf[1] = Vs[kk*8 + c + 4][nt*8 + r];
                mma_tf32(of[nt], af, bf, of[nt]);
            }
        }
    }

    const int b = bh >> 4, h = bh & 15;
    const float inv0 = 1.0f / l0i;
    const float inv1 = 1.0f / l1i;
    const int qg0 = qbase + r;
    #pragma unroll
    for (int nt = 0; nt < 8; nt++) {
        const int d = nt*8 + c*2;
        float* o0 = g_ctx + ((size_t)(b*SS + qg0    ))*DD + h*HDIM + d;
        float* o1 = g_ctx + ((size_t)(b*SS + qg0 + 8))*DD + h*HDIM + d;
        o0[0] = of[nt][0] * inv0;
        o0[1] = of[nt][1] * inv0;
        o1[0] = of[nt][2] * inv1;
        o1[1] = of[nt][3] * inv1;
    }
}

// ---------------------------------------------------------------------------
// Launch
// ---------------------------------------------------------------------------
extern "C" void kernel_launch(void* const* d_in, const int* in_sizes, int n_in,
                              void* d_out, int out_size)
{
    const float* x  = (const float*)d_in[0];
    const float* Wq = (const float*)d_in[1];
    const float* Wk = (const float*)d_in[2];
    const float* Wv = (const float*)d_in[3];
    const float* Wo = (const float*)d_in[4];
    const float* bo = (const float*)d_in[5];
    float* out = (float*)d_out;

    (void)in_sizes; (void)n_in; (void)out_size;

    cudaFuncSetAttribute(qkv_gemm_kernel,
                         cudaFuncAttributeMaxDynamicSharedMemorySize, SMEM_GEMM);
    qkv_gemm_kernel<<<dim3(8, 32, 3), 256, SMEM_GEMM>>>(x, Wq, Wk, Wv);

    const int attn_smem = (2*64*KVPAD + 128*PPAD) * 4;   // 71680
    cudaFuncSetAttribute(attn_kernel,
                         cudaFuncAttributeMaxDynamicSharedMemorySize, attn_smem);
    attn_kernel<<<dim3(16, 32), 256, attn_smem>>>();

    cudaFuncSetAttribute(oproj_kernel,
                         cudaFuncAttributeMaxDynamicSharedMemorySize, SMEM_GEMM);
    oproj_kernel<<<dim3(8, 32), 256, SMEM_GEMM>>>(Wo, bo, out);
}

// round 5
// speedup vs baseline: 4.2444x; 1.7283x over previous
#include <cuda_runtime.h>
#include <cuda_fp16.h>
#include <math.h>
#include <stdint.h>

#define BB   2
#define SS   2048
#define DD   1024
#define NH   16
#define HDIM 64
#define NTOK (BB*SS)

// Scratch (device globals: allocation-free per harness rules), fp16
__device__ __half g_q[NTOK*DD];    // [b][h][s][d], pre-scaled by 0.125
__device__ __half g_k[NTOK*DD];    // [b][h][s][d]
__device__ __half g_v[NTOK*DD];    // [b][h][s][d]
__device__ __half g_ctx[NTOK*DD];  // [b][s][h*64+d]

// ---------------------------------------------------------------------------
// Helpers
// ---------------------------------------------------------------------------
__device__ __forceinline__ uint32_t smem_u32(const void* p) {
    uint32_t a;
    asm("{ .reg .u64 t; cvta.to.shared.u64 t, %1; cvt.u32.u64 %0, t; }"
        : "=r"(a) : "l"(p));
    return a;
}
__device__ __forceinline__ uint32_t f2h2(float lo, float hi) {
    __half2 h = __floats2half2_rn(lo, hi);
    return *reinterpret_cast<uint32_t*>(&h);
}
__device__ __forceinline__ void mma_f16(float d[4], const uint32_t a[4],
                                        const uint32_t* b, const float c[4]) {
    asm volatile(
        "mma.sync.aligned.m16n8k16.row.col.f32.f16.f16.f32 "
        "{%0,%1,%2,%3}, {%4,%5,%6,%7}, {%8,%9}, {%10,%11,%12,%13};"
        : "=f"(d[0]), "=f"(d[1]), "=f"(d[2]), "=f"(d[3])
        : "r"(a[0]), "r"(a[1]), "r"(a[2]), "r"(a[3]),
          "r"(b[0]), "r"(b[1]),
          "f"(c[0]), "f"(c[1]), "f"(c[2]), "f"(c[3]));
}
__device__ __forceinline__ void lds128(uint32_t r[4], uint32_t addr) {
    asm volatile("ld.shared.v4.b32 {%0,%1,%2,%3}, [%4];"
        : "=r"(r[0]), "=r"(r[1]), "=r"(r[2]), "=r"(r[3]) : "r"(addr));
}
__device__ __forceinline__ void sts32(uint32_t addr, uint32_t v) {
    asm volatile("st.shared.b32 [%0], %1;" :: "r"(addr), "r"(v) : "memory");
}

// ---------------------------------------------------------------------------
// fp16 fragment-packed GEMM: C(128x128) = A[m0:+128,:] @ W[n0:+128,:]^T, K=1024.
// 256 threads = 8 warps (2x4), warp tile 64x32, BK=32 (2 k16 steps), dbl buffer.
// Per buffer (16KB): A at +0 (8KB): ks*4096 + tile16*512 + lane*16 + reg*4
//                    B at +8192 (8KB): ntile*512 + lane*16 + ks*8 + reg*4
// ---------------------------------------------------------------------------
#define GBUF 16384u

__device__ __forceinline__ void stage_f16(
    uint32_t sb, const uint32_t pa2[4][2], const uint32_t pb2[4][2],
    int lrow, int lci)
{
    const int c_ = (lci & 1) * 2;
    const int kh = (lci >> 1) & 1;
    const int ks = lci >> 2;
    #pragma unroll
    for (int p = 0; p < 4; p++) {
        const int row = lrow + p*32;
        const int t16 = row >> 4, hi = (row >> 3) & 1, rr = row & 7;
        const uint32_t aadr = sb + (uint32_t)(ks*4096 + t16*512 + (rr*4 + c_)*16 + (hi + 2*kh)*4);
        sts32(aadr,      pa2[p][0]);
        sts32(aadr + 16, pa2[p][1]);
        const int ntl = row >> 3, rn = row & 7;
        const uint32_t badr = sb + 8192u + (uint32_t)(ntl*512 + (rn*4 + c_)*16 + ks*8 + kh*4);
        sts32(badr,      pb2[p][0]);
        sts32(badr + 16, pb2[p][1]);
    }
}

template<bool A_HALF>
__device__ __forceinline__ void tc_gemm_core(
    const void* Av, const float* __restrict__ W,
    int m0, int n0, uint32_t sbase, float acc[4][4][4])
{
    const int tid  = threadIdx.x;
    const int lane = tid & 31;
    const int warp = tid >> 5;
    const int wm = warp >> 2;
    const int wn = warp & 3;
    const int lrow = tid >> 3;           // 0..31
    const int lci  = tid & 7;            // 16B chunk of 64B(half) k-row

    const uint32_t a_rd = sbase + (uint32_t)((wm*4)*512 + lane*16);
    const uint32_t b_rd = sbase + 8192u + (uint32_t)((wn*4)*512 + lane*16);

    const float*  Af = (const float*)Av;
    const __half* Ah = (const __half*)Av;

    // raw prefetch registers
    float4 fa[4]; uint2 ua[4]; float4 fb[4];
    uint32_t pa2[4][2], pb2[4][2];

    // chunk 0 load + stage
    #pragma unroll
    for (int p = 0; p < 4; p++) {
        const size_t roff = (size_t)(m0 + lrow + p*32) * DD + lci*4;
        if (A_HALF) { ua[p] = *reinterpret_cast<const uint2*>(Ah + roff); }
        else        { fa[p] = *reinterpret_cast<const float4*>(Af + roff); }
        fb[p] = *reinterpret_cast<const float4*>(W + (size_t)(n0 + lrow + p*32)*DD + lci*4);
    }
    #pragma unroll
    for (int p = 0; p < 4; p++) {
        if (A_HALF) { pa2[p][0] = ua[p].x; pa2[p][1] = ua[p].y; }
        else        { pa2[p][0] = f2h2(fa[p].x, fa[p].y); pa2[p][1] = f2h2(fa[p].z, fa[p].w); }
        pb2[p][0] = f2h2(fb[p].x, fb[p].y);
        pb2[p][1] = f2h2(fb[p].z, fb[p].w);
    }
    stage_f16(sbase, pa2, pb2, lrow, lci);
    __syncthreads();

    for (int i = 0; i < 32; i++) {
        const uint32_t bufo = (uint32_t)(i & 1) * GBUF;
        // prefetch next chunk (raw, kept live through mma phase)
        if (i + 1 < 32) {
            const int k0 = (i + 1) * 32;
            #pragma unroll
            for (int p = 0; p < 4; p++) {
                const size_t roff = (size_t)(m0 + lrow + p*32) * DD + k0 + lci*4;
                if (A_HALF) { ua[p] = *reinterpret_cast<const uint2*>(Ah + roff); }
                else        { fa[p] = *reinterpret_cast<const float4*>(Af + roff); }
                fb[p] = *reinterpret_cast<const float4*>(W + (size_t)(n0 + lrow + p*32)*DD + k0 + lci*4);
            }
        }

        // compute: 2 k16 steps, 32 HMMA
        uint32_t bfr[4][4];
        #pragma unroll
        for (int nt = 0; nt < 4; nt++)
            lds128(bfr[nt], b_rd + bufo + (uint32_t)(nt*512));
        #pragma unroll
        for (int ks = 0; ks < 2; ks++) {
            uint32_t af[4][4];
            #pragma unroll
            for (int mt = 0; mt < 4; mt++)
                lds128(af[mt], a_rd + bufo + (uint32_t)(ks*4096 + mt*512));
            #pragma unroll
            for (int mt = 0; mt < 4; mt++)
                #pragma unroll
                for (int nt = 0; nt < 4; nt++)
                    mma_f16(acc[mt][nt], af[mt], &bfr[nt][ks*2], acc[mt][nt]);
        }

        // stage next chunk into other buffer
        if (i + 1 < 32) {
            #pragma unroll
            for (int p = 0; p < 4; p++) {
                if (A_HALF) { pa2[p][0] = ua[p].x; pa2[p][1] = ua[p].y; }
                else        { pa2[p][0] = f2h2(fa[p].x, fa[p].y); pa2[p][1] = f2h2(fa[p].z, fa[p].w); }
                pb2[p][0] = f2h2(fb[p].x, fb[p].y);
                pb2[p][1] = f2h2(fb[p].z, fb[p].w);
            }
            stage_f16(sbase + (GBUF - bufo), pa2, pb2, lrow, lci);
        }
        __syncthreads();
    }
}

// ---------------------------------------------------------------------------
// Kernel 1: fused QKV projection. grid (8, 32, 3), block 256. fp16 output.
// ---------------------------------------------------------------------------
__global__ __launch_bounds__(256) void qkv_gemm_kernel(
    const float* __restrict__ x,
    const float* __restrict__ Wq,
    const float* __restrict__ Wk,
    const float* __restrict__ Wv)
{
    __shared__ __align__(16) uint32_t smg[2*GBUF/4];
    const uint32_t sbase = smem_u32(smg);

    const float* W    = (blockIdx.z == 0) ? Wq : (blockIdx.z == 1) ? Wk : Wv;
    __half*      out  = (blockIdx.z == 0) ? g_q : (blockIdx.z == 1) ? g_k : g_v;
    const float oscale = (blockIdx.z == 0) ? 0.125f : 1.0f;   // fold 1/sqrt(64) into q

    const int m0 = blockIdx.y * 128;
    const int n0 = blockIdx.x * 128;

    float acc[4][4][4];
    #pragma unroll
    for (int i = 0; i < 4; i++)
        #pragma unroll
        for (int j = 0; j < 4; j++)
            #pragma unroll
            for (int k = 0; k < 4; k++) acc[i][j][k] = 0.f;

    tc_gemm_core<false>(x, W, m0, n0, sbase, acc);

    const int lane = threadIdx.x & 31;
    const int warp = threadIdx.x >> 5;
    const int wm = warp >> 2, wn = warp & 3;
    const int r = lane >> 2, c = lane & 3;

    #pragma unroll
    for (int mt = 0; mt < 4; mt++) {
        #pragma unroll
        for (int nt = 0; nt < 4; nt++) {
            #pragma unroll
            for (int half = 0; half < 2; half++) {
                const int m = m0 + wm*64 + mt*16 + r + half*8;
                const int b = m >> 11;
                const int s = m & 2047;
                const int n = n0 + wn*32 + nt*8 + c*2;
                const int h = n >> 6;
                const int d = n & 63;
                const uint32_t v = f2h2(acc[mt][nt][half*2+0]*oscale,
                                        acc[mt][nt][half*2+1]*oscale);
                *reinterpret_cast<uint32_t*>(
                    out + (((size_t)(b*NH + h))*SS + s)*HDIM + d) = v;
            }
        }
    }
}

// ---------------------------------------------------------------------------
// Kernel 3: output projection + bias (A = g_ctx fp16). grid (8, 32), block 256.
// ---------------------------------------------------------------------------
__global__ __launch_bounds__(256) void oproj_kernel(
    const float* __restrict__ Wo,
    const float* __restrict__ bo,
    float* __restrict__ out)
{
    __shared__ __align__(16) uint32_t smg[2*GBUF/4];
    const uint32_t sbase = smem_u32(smg);

    const int m0 = blockIdx.y * 128;
    const int n0 = blockIdx.x * 128;

    float acc[4][4][4];
    #pragma unroll
    for (int i = 0; i < 4; i++)
        #pragma unroll
        for (int j = 0; j < 4; j++)
            #pragma unroll
            for (int k = 0; k < 4; k++) acc[i][j][k] = 0.f;

    tc_gemm_core<true>(g_ctx, Wo, m0, n0, sbase, acc);

    const int lane = threadIdx.x & 31;
    const int warp = threadIdx.x >> 5;
    const int wm = warp >> 2, wn = warp & 3;
    const int r = lane >> 2, c = lane & 3;

    #pragma unroll
    for (int mt = 0; mt < 4; mt++) {
        #pragma unroll
        for (int nt = 0; nt < 4; nt++) {
            #pragma unroll
            for (int half = 0; half < 2; half++) {
                const int m = m0 + wm*64 + mt*16 + r + half*8;
                const int n = n0 + wn*32 + nt*8 + c*2;
                float* o = out + (size_t)m*DD + n;
                o[0] = acc[mt][nt][half*2 + 0] + bo[n];
                o[1] = acc[mt][nt][half*2 + 1] + bo[n + 1];
            }
        }
    }
}

// ---------------------------------------------------------------------------
// Kernel 2: causal flash attention, fp16 mma.m16n8k16.
// grid (16 q-tiles, 32 bh), block 256 (8 warps, 16 q-rows/warp), KV tile 64.
// Smem (u32): Ks[d2=32][72] (pairs along d), Vs[key2=32][72] (pairs along key),
//             Ps[q=128][40] (pairs along key). 38,912 B -> 2 CTAs/SM.
// ---------------------------------------------------------------------------
__global__ __launch_bounds__(256) void attn_kernel()
{
    __shared__ uint32_t Ks[32][72];
    __shared__ uint32_t Vs[32][72];
    __shared__ uint32_t Ps[128][40];

    const int tid  = threadIdx.x;
    const int lane = tid & 31;
    const int warp = tid >> 5;
    const int r = lane >> 2;
    const int c = lane & 3;
    const int qt = blockIdx.x;
    const int bh = blockIdx.y;

    const __half* Qg = g_q + (size_t)bh * SS * HDIM;
    const __half* Kg = g_k + (size_t)bh * SS * HDIM;
    const __half* Vg = g_v + (size_t)bh * SS * HDIM;
    const uint32_t* Qg2 = reinterpret_cast<const uint32_t*>(Qg);
    const int q0 = qt * 128;
    const int qbase = q0 + warp * 16;

    // Q fragments (g_q pre-scaled by 0.125)
    uint32_t qf[4][4];
    #pragma unroll
    for (int kk = 0; kk < 4; kk++) {
        qf[kk][0] = Qg2[(size_t)(qbase + r    )*32 + kk*8 + c    ];
        qf[kk][1] = Qg2[(size_t)(qbase + r + 8)*32 + kk*8 + c    ];
        qf[kk][2] = Qg2[(size_t)(qbase + r    )*32 + kk*8 + c + 4];
        qf[kk][3] = Qg2[(size_t)(qbase + r + 8)*32 + kk*8 + c + 4];
    }

    float of[8][4];
    #pragma unroll
    for (int nt = 0; nt < 8; nt++)
        #pragma unroll
        for (int j = 0; j < 4; j++) of[nt][j] = 0.f;
    float m0i = -1e30f, m1i = -1e30f, l0i = 0.f, l1i = 0.f;

    const int ktmax = 2*qt + 1;
    for (int kt = 0; kt <= ktmax; kt++) {
        __syncthreads();
        // stage K: Ks[d2][key]; uint2 = 4 halves = 2 pairs along d
        #pragma unroll
        for (int it = 0; it < 4; it++) {
            const int idx = tid + it*256;
            const int row = idx >> 4;            // key
            const int d4  = (idx & 15) * 4;
            const uint2 kv = *reinterpret_cast<const uint2*>(Kg + (size_t)(kt*64+row)*HDIM + d4);
            Ks[(d4>>1)    ][row] = kv.x;
            Ks[(d4>>1) + 1][row] = kv.y;
        }
        // stage V: Vs[key2][d]; pairs along key via byte_perm of two key rows
        #pragma unroll
        for (int it = 0; it < 2; it++) {
            const int idx = tid + it*256;
            const int m  = idx >> 4;             // key pair 0..31
            const int d4 = (idx & 15) * 4;
            const uint2 va = *reinterpret_cast<const uint2*>(Vg + (size_t)(kt*64 + 2*m    )*HDIM + d4);
            const uint2 vb = *reinterpret_cast<const uint2*>(Vg + (size_t)(kt*64 + 2*m + 1)*HDIM + d4);
            Vs[m][d4+0] = __byte_perm(va.x, vb.x, 0x5410);
            Vs[m][d4+1] = __byte_perm(va.x, vb.x, 0x7632);
            Vs[m][d4+2] = __byte_perm(va.y, vb.y, 0x5410);
            Vs[m][d4+3] = __byte_perm(va.y, vb.y, 0x7632);
        }
        __syncthreads();

        if (kt*64 > qbase + 15) continue;  // causal early-exit for this warp

        // S = Q @ K^T : 4 k16-steps x 8 n-tiles
        float sf[8][4];
        #pragma unroll
        for (int nt = 0; nt < 8; nt++)
            #pragma unroll
            for (int j = 0; j < 4; j++) sf[nt][j] = 0.f;

        #pragma unroll
        for (int kk = 0; kk < 4; kk++) {
            #pragma unroll
            for (int nt = 0; nt < 8; nt++) {
                uint32_t bf[2];
                bf[0] = Ks[kk*8 + c    ][nt*8 + r];
                bf[1] = Ks[kk*8 + c + 4][nt*8 + r];
                mma_f16(sf[nt], qf[kk], bf, sf[nt]);
            }
        }

        // causal mask (scores already scaled via pre-scaled Q)
        const int qg0 = qbase + r;
        const int qg1 = qg0 + 8;
        #pragma unroll
        for (int nt = 0; nt < 8; nt++) {
            const int col0 = kt*64 + nt*8 + c*2;
            if (col0     > qg0) sf[nt][0] = -1e30f;
            if (col0 + 1 > qg0) sf[nt][1] = -1e30f;
            if (col0     > qg1) sf[nt][2] = -1e30f;
            if (col0 + 1 > qg1) sf[nt][3] = -1e30f;
        }

        float mx0 = -1e30f, mx1 = -1e30f;
        #pragma unroll
        for (int nt = 0; nt < 8; nt++) {
            mx0 = fmaxf(mx0, fmaxf(sf[nt][0], sf[nt][1]));
            mx1 = fmaxf(mx1, fmaxf(sf[nt][2], sf[nt][3]));
        }
        mx0 = fmaxf(mx0, __shfl_xor_sync(0xffffffffu, mx0, 1));
        mx0 = fmaxf(mx0, __shfl_xor_sync(0xffffffffu, mx0, 2));
        mx1 = fmaxf(mx1, __shfl_xor_sync(0xffffffffu, mx1, 1));
        mx1 = fmaxf(mx1, __shfl_xor_sync(0xffffffffu, mx1, 2));

        const float mn0 = fmaxf(m0i, mx0);
        const float mn1 = fmaxf(m1i, mx1);
        const float cor0 = __expf(m0i - mn0);
        const float cor1 = __expf(m1i - mn1);

        float s0 = 0.f, s1 = 0.f;
        #pragma unroll
        for (int nt = 0; nt < 8; nt++) {
            const float p00 = __expf(sf[nt][0] - mn0);
            const float p01 = __expf(sf[nt][1] - mn0);
            const float p10 = __expf(sf[nt][2] - mn1);
            const float p11 = __expf(sf[nt][3] - mn1);
            s0 += p00 + p01;
            s1 += p10 + p11;
            Ps[warp*16 + r    ][nt*4 + c] = f2h2(p00, p01);
            Ps[warp*16 + r + 8][nt*4 + c] = f2h2(p10, p11);
        }
        s0 += __shfl_xor_sync(0xffffffffu, s0, 1);
        s0 += __shfl_xor_sync(0xffffffffu, s0, 2);
        s1 += __shfl_xor_sync(0xffffffffu, s1, 1);
        s1 += __shfl_xor_sync(0xffffffffu, s1, 2);

        l0i = l0i * cor0 + s0;
        l1i = l1i * cor1 + s1;
        m0i = mn0;
        m1i = mn1;

        #pragma unroll
        for (int nt = 0; nt < 8; nt++) {
            of[nt][0] *= cor0;
            of[nt][1] *= cor0;
            of[nt][2] *= cor1;
            of[nt][3] *= cor1;
        }

        __syncwarp();   // Ps rows are per-warp private

        // O += P @ V : 4 k16-steps (over keys) x 8 d-tiles
        #pragma unroll
        for (int kk = 0; kk < 4; kk++) {
            uint32_t af[4];
            af[0] = Ps[warp*16 + r    ][kk*8 + c    ];
            af[1] = Ps[warp*16 + r + 8][kk*8 + c    ];
            af[2] = Ps[warp*16 + r    ][kk*8 + c + 4];
            af[3] = Ps[warp*16 + r + 8][kk*8 + c + 4];
            #pragma unroll
            for (int nt = 0; nt < 8; nt++) {
                uint32_t bf[2];
                bf[0] = Vs[kk*8 + c    ][nt*8 + r];
                bf[1] = Vs[kk*8 + c + 4][nt*8 + r];
                mma_f16(of[nt], af, bf, of[nt]);
            }
        }
    }

    // epilogue: normalize, write ctx (fp16) [b][s][h*64+d]
    const int b = bh >> 4, h = bh & 15;
    const float inv0 = 1.0f / l0i;
    const float inv1 = 1.0f / l1i;
    const int qg0 = qbase + r;
    #pragma unroll
    for (int nt = 0; nt < 8; nt++) {
        const int d = nt*8 + c*2;
        *reinterpret_cast<uint32_t*>(
            g_ctx + ((size_t)(b*SS + qg0    ))*DD + h*HDIM + d) = f2h2(of[nt][0]*inv0, of[nt][1]*inv0);
        *reinterpret_cast<uint32_t*>(
            g_ctx + ((size_t)(b*SS + qg0 + 8))*DD + h*HDIM + d) = f2h2(of[nt][2]*inv1, of[nt][3]*inv1);
    }
}

// ---------------------------------------------------------------------------
// Launch
// ---------------------------------------------------------------------------
extern "C" void kernel_launch(void* const* d_in, const int* in_sizes, int n_in,
                              void* d_out, int out_size)
{
    const float* x  = (const float*)d_in[0];
    const float* Wq = (const float*)d_in[1];
    const float* Wk = (const float*)d_in[2];
    const float* Wv = (const float*)d_in[3];
    const float* Wo = (const float*)d_in[4];
    const float* bo = (const float*)d_in[5];
    float* out = (float*)d_out;

    (void)in_sizes; (void)n_in; (void)out_size;

    qkv_gemm_kernel<<<dim3(8, 32, 3), 256>>>(x, Wq, Wk, Wv);
    attn_kernel<<<dim3(16, 32), 256>>>();
    oproj_kernel<<<dim3(8, 32), 256>>>(Wo, bo, out);
}

// round 6
// speedup vs baseline: 5.1436x; 1.2118x over previous
#include <cuda_runtime.h>
#include <cuda_fp16.h>
#include <math.h>
#include <stdint.h>

#define BB   2
#define SS   2048
#define DD   1024
#define NH   16
#define HDIM 64
#define NTOK (BB*SS)

// Scratch (device globals: allocation-free per harness rules)
__device__ __half g_q[NTOK*DD];    // [b][h][s][d], pre-scaled by 0.125
__device__ __half g_k[NTOK*DD];
__device__ __half g_v[NTOK*DD];
__device__ __half g_ctx[NTOK*DD];  // [b][s][h*64+d]
__device__ __half g_x16[NTOK*DD];  // fp16 copy of x
__device__ __half g_wq16[DD*DD];
__device__ __half g_wk16[DD*DD];
__device__ __half g_wv16[DD*DD];
__device__ __half g_wo16[DD*DD];

// ---------------------------------------------------------------------------
// Helpers
// ---------------------------------------------------------------------------
__device__ __forceinline__ uint32_t smem_u32(const void* p) {
    uint32_t a;
    asm("{ .reg .u64 t; cvta.to.shared.u64 t, %1; cvt.u32.u64 %0, t; }"
        : "=r"(a) : "l"(p));
    return a;
}
__device__ __forceinline__ uint32_t f2h2(float lo, float hi) {
    __half2 h = __floats2half2_rn(lo, hi);
    return *reinterpret_cast<uint32_t*>(&h);
}
__device__ __forceinline__ void mma_f16(float d[4], const uint32_t a[4],
                                        const uint32_t* b, const float c[4]) {
    asm volatile(
        "mma.sync.aligned.m16n8k16.row.col.f32.f16.f16.f32 "
        "{%0,%1,%2,%3}, {%4,%5,%6,%7}, {%8,%9}, {%10,%11,%12,%13};"
        : "=f"(d[0]), "=f"(d[1]), "=f"(d[2]), "=f"(d[3])
        : "r"(a[0]), "r"(a[1]), "r"(a[2]), "r"(a[3]),
          "r"(b[0]), "r"(b[1]),
          "f"(c[0]), "f"(c[1]), "f"(c[2]), "f"(c[3]));
}
__device__ __forceinline__ void ldsm_x4(uint32_t r[4], uint32_t addr) {
    asm volatile("ldmatrix.sync.aligned.m8n8.x4.shared.b16 {%0,%1,%2,%3}, [%4];"
        : "=r"(r[0]), "=r"(r[1]), "=r"(r[2]), "=r"(r[3]) : "r"(addr));
}
__device__ __forceinline__ void cp_async16(uint32_t saddr, const void* gaddr) {
    asm volatile("cp.async.cg.shared.global [%0], [%1], 16;"
        :: "r"(saddr), "l"(gaddr) : "memory");
}

// ---------------------------------------------------------------------------
// Kernel 0: fp32 -> fp16 convert (grid-stride over float4)
// ---------------------------------------------------------------------------
__global__ __launch_bounds__(256) void cvt_kernel(const float4* __restrict__ src,
                                                  uint2* __restrict__ dst, int n4)
{
    const int i = blockIdx.x * 256 + threadIdx.x;
    if (i < n4) {
        const float4 v = src[i];
        uint2 o;
        o.x = f2h2(v.x, v.y);
        o.y = f2h2(v.z, v.w);
        dst[i] = o;
    }
}

// ---------------------------------------------------------------------------
// fp16 GEMM core: C(128x128) = A[m0:+128,:] @ B[n0:+128,:]^T, K=1024, fp16 in.
// 256 thr = 8 warps (2x4), warp tile 64x32, BK=32, 3-stage cp.async pipeline.
// Smem/stage 16KB: A tile 128x32h at +0, B tile 128x32h at +8192.
// Swizzle: byte = row*64 + ((chunk ^ ((row>>1)&3))*16), chunk = k>>3.
// ---------------------------------------------------------------------------
#define GSTG 16384u

__device__ __forceinline__ void gemm16_stage(
    const __half* __restrict__ A, const __half* __restrict__ B,
    int m0, int n0, uint32_t sbase, int s, int k0, int tid)
{
    #pragma unroll
    for (int j = 0; j < 2; j++) {
        const int id  = tid + j*256;
        const int row = id >> 2;
        const int ch  = id & 3;
        const uint32_t sw = (uint32_t)(row*64 + ((ch ^ ((row>>1)&3))*16));
        cp_async16(sbase + (uint32_t)s*GSTG + sw,
                   A + (size_t)(m0 + row)*DD + k0 + ch*8);
        cp_async16(sbase + (uint32_t)s*GSTG + 8192u + sw,
                   B + (size_t)(n0 + row)*DD + k0 + ch*8);
    }
    asm volatile("cp.async.commit_group;" ::: "memory");
}

__device__ __forceinline__ void gemm16_core(
    const __half* __restrict__ A, const __half* __restrict__ B,
    int m0, int n0, uint32_t sbase, float acc[4][4][4])
{
    const int tid  = threadIdx.x;
    const int lane = tid & 31;
    const int warp = tid >> 5;
    const int wm = warp >> 2;
    const int wn = warp & 3;

    // ldmatrix lane-address components (fixed per thread)
    const int a_row_off = (lane & 7) + ((lane >> 3) & 1) * 8;  // within m-tile
    const int a_ch_off  = lane >> 4;                           // 0/1
    const int b_row_off = ((lane >> 4) << 3) + (lane & 7);     // within n-pair
    const int b_ch_off  = (lane >> 3) & 1;                     // 0/1

    gemm16_stage(A, B, m0, n0, sbase, 0, 0, tid);
    gemm16_stage(A, B, m0, n0, sbase, 1, 32, tid);

    for (int i = 0; i < 32; i++) {
        const int s = i - (i/3)*3;
        if (i >= 30) { asm volatile("cp.async.wait_group 0;" ::: "memory"); }
        else         { asm volatile("cp.async.wait_group 1;" ::: "memory"); }
        __syncthreads();

        if (i + 2 < 32) {
            const int s2 = (i+2) - ((i+2)/3)*3;
            gemm16_stage(A, B, m0, n0, sbase, s2, (i+2)*32, tid);
        }

        const uint32_t sA = sbase + (uint32_t)s*GSTG;
        const uint32_t sB = sA + 8192u;

        #pragma unroll
        for (int ks = 0; ks < 2; ks++) {
            uint32_t af[4][4];
            #pragma unroll
            for (int mt = 0; mt < 4; mt++) {
                const int row = wm*64 + mt*16 + a_row_off;
                const int ch  = 2*ks + a_ch_off;
                ldsm_x4(af[mt], sA + (uint32_t)(row*64 + ((ch ^ ((row>>1)&3))*16)));
            }
            uint32_t bf[4][2];
            #pragma unroll
            for (int pr = 0; pr < 2; pr++) {
                const int row = wn*32 + pr*16 + b_row_off;
                const int ch  = 2*ks + b_ch_off;
                uint32_t t[4];
                ldsm_x4(t, sB + (uint32_t)(row*64 + ((ch ^ ((row>>1)&3))*16)));
                bf[pr*2  ][0] = t[0]; bf[pr*2  ][1] = t[1];
                bf[pr*2+1][0] = t[2]; bf[pr*2+1][1] = t[3];
            }
            #pragma unroll
            for (int mt = 0; mt < 4; mt++)
                #pragma unroll
                for (int nt = 0; nt < 4; nt++)
                    mma_f16(acc[mt][nt], af[mt], bf[nt], acc[mt][nt]);
        }
    }
}

// ---------------------------------------------------------------------------
// Kernel 1: fused QKV projection. grid (8, 32, 3), block 256. fp16 in/out.
// ---------------------------------------------------------------------------
__global__ __launch_bounds__(256) void qkv_gemm_kernel()
{
    __shared__ __align__(16) char smg[3*GSTG];
    const uint32_t sbase = smem_u32(smg);

    const __half* W   = (blockIdx.z == 0) ? g_wq16 : (blockIdx.z == 1) ? g_wk16 : g_wv16;
    __half*       out = (blockIdx.z == 0) ? g_q    : (blockIdx.z == 1) ? g_k    : g_v;
    const float oscale = (blockIdx.z == 0) ? 0.125f : 1.0f;

    const int m0 = blockIdx.y * 128;
    const int n0 = blockIdx.x * 128;

    float acc[4][4][4];
    #pragma unroll
    for (int i = 0; i < 4; i++)
        #pragma unroll
        for (int j = 0; j < 4; j++)
            #pragma unroll
            for (int k = 0; k < 4; k++) acc[i][j][k] = 0.f;

    gemm16_core(g_x16, W, m0, n0, sbase, acc);

    const int lane = threadIdx.x & 31;
    const int warp = threadIdx.x >> 5;
    const int wm = warp >> 2, wn = warp & 3;
    const int r = lane >> 2, c = lane & 3;

    #pragma unroll
    for (int mt = 0; mt < 4; mt++) {
        #pragma unroll
        for (int nt = 0; nt < 4; nt++) {
            #pragma unroll
            for (int half = 0; half < 2; half++) {
                const int m = m0 + wm*64 + mt*16 + r + half*8;
                const int b = m >> 11;
                const int s = m & 2047;
                const int n = n0 + wn*32 + nt*8 + c*2;
                const int h = n >> 6;
                const int d = n & 63;
                const uint32_t v = f2h2(acc[mt][nt][half*2+0]*oscale,
                                        acc[mt][nt][half*2+1]*oscale);
                *reinterpret_cast<uint32_t*>(
                    out + (((size_t)(b*NH + h))*SS + s)*HDIM + d) = v;
            }
        }
    }
}

// ---------------------------------------------------------------------------
// Kernel 3: output projection + bias. grid (8, 32), block 256.
// ---------------------------------------------------------------------------
__global__ __launch_bounds__(256) void oproj_kernel(
    const float* __restrict__ bo,
    float* __restrict__ out)
{
    __shared__ __align__(16) char smg[3*GSTG];
    const uint32_t sbase = smem_u32(smg);

    const int m0 = blockIdx.y * 128;
    const int n0 = blockIdx.x * 128;

    float acc[4][4][4];
    #pragma unroll
    for (int i = 0; i < 4; i++)
        #pragma unroll
        for (int j = 0; j < 4; j++)
            #pragma unroll
            for (int k = 0; k < 4; k++) acc[i][j][k] = 0.f;

    gemm16_core(g_ctx, g_wo16, m0, n0, sbase, acc);

    const int lane = threadIdx.x & 31;
    const int warp = threadIdx.x >> 5;
    const int wm = warp >> 2, wn = warp & 3;
    const int r = lane >> 2, c = lane & 3;

    #pragma unroll
    for (int mt = 0; mt < 4; mt++) {
        #pragma unroll
        for (int nt = 0; nt < 4; nt++) {
            #pragma unroll
            for (int half = 0; half < 2; half++) {
                const int m = m0 + wm*64 + mt*16 + r + half*8;
                const int n = n0 + wn*32 + nt*8 + c*2;
                float* o = out + (size_t)m*DD + n;
                o[0] = acc[mt][nt][half*2 + 0] + bo[n];
                o[1] = acc[mt][nt][half*2 + 1] + bo[n + 1];
            }
        }
    }
}

// ---------------------------------------------------------------------------
// Kernel 2: causal flash attention, fp16 mma.m16n8k16 (unchanged from R5).
// ---------------------------------------------------------------------------
__global__ __launch_bounds__(256) void attn_kernel()
{
    __shared__ uint32_t Ks[32][72];
    __shared__ uint32_t Vs[32][72];
    __shared__ uint32_t Ps[128][40];

    const int tid  = threadIdx.x;
    const int lane = tid & 31;
    const int warp = tid >> 5;
    const int r = lane >> 2;
    const int c = lane & 3;
    const int qt = blockIdx.x;
    const int bh = blockIdx.y;

    const __half* Qg = g_q + (size_t)bh * SS * HDIM;
    const __half* Kg = g_k + (size_t)bh * SS * HDIM;
    const __half* Vg = g_v + (size_t)bh * SS * HDIM;
    const uint32_t* Qg2 = reinterpret_cast<const uint32_t*>(Qg);
    const int q0 = qt * 128;
    const int qbase = q0 + warp * 16;

    uint32_t qf[4][4];
    #pragma unroll
    for (int kk = 0; kk < 4; kk++) {
        qf[kk][0] = Qg2[(size_t)(qbase + r    )*32 + kk*8 + c    ];
        qf[kk][1] = Qg2[(size_t)(qbase + r + 8)*32 + kk*8 + c    ];
        qf[kk][2] = Qg2[(size_t)(qbase + r    )*32 + kk*8 + c + 4];
        qf[kk][3] = Qg2[(size_t)(qbase + r + 8)*32 + kk*8 + c + 4];
    }

    float of[8][4];
    #pragma unroll
    for (int nt = 0; nt < 8; nt++)
        #pragma unroll
        for (int j = 0; j < 4; j++) of[nt][j] = 0.f;
    float m0i = -1e30f, m1i = -1e30f, l0i = 0.f, l1i = 0.f;

    const int ktmax = 2*qt + 1;
    for (int kt = 0; kt <= ktmax; kt++) {
        __syncthreads();
        #pragma unroll
        for (int it = 0; it < 4; it++) {
            const int idx = tid + it*256;
            const int row = idx >> 4;
            const int d4  = (idx & 15) * 4;
            const uint2 kv = *reinterpret_cast<const uint2*>(Kg + (size_t)(kt*64+row)*HDIM + d4);
            Ks[(d4>>1)    ][row] = kv.x;
            Ks[(d4>>1) + 1][row] = kv.y;
        }
        #pragma unroll
        for (int it = 0; it < 2; it++) {
            const int idx = tid + it*256;
            const int m  = idx >> 4;
            const int d4 = (idx & 15) * 4;
            const uint2 va = *reinterpret_cast<const uint2*>(Vg + (size_t)(kt*64 + 2*m    )*HDIM + d4);
            const uint2 vb = *reinterpret_cast<const uint2*>(Vg + (size_t)(kt*64 + 2*m + 1)*HDIM + d4);
            Vs[m][d4+0] = __byte_perm(va.x, vb.x, 0x5410);
            Vs[m][d4+1] = __byte_perm(va.x, vb.x, 0x7632);
            Vs[m][d4+2] = __byte_perm(va.y, vb.y, 0x5410);
            Vs[m][d4+3] = __byte_perm(va.y, vb.y, 0x7632);
        }
        __syncthreads();

        if (kt*64 > qbase + 15) continue;

        float sf[8][4];
        #pragma unroll
        for (int nt = 0; nt < 8; nt++)
            #pragma unroll
            for (int j = 0; j < 4; j++) sf[nt][j] = 0.f;

        #pragma unroll
        for (int kk = 0; kk < 4; kk++) {
            #pragma unroll
            for (int nt = 0; nt < 8; nt++) {
                uint32_t bf[2];
                bf[0] = Ks[kk*8 + c    ][nt*8 + r];
                bf[1] = Ks[kk*8 + c + 4][nt*8 + r];
                mma_f16(sf[nt], qf[kk], bf, sf[nt]);
            }
        }

        const int qg0 = qbase + r;
        const int qg1 = qg0 + 8;
        #pragma unroll
        for (int nt = 0; nt < 8; nt++) {
            const int col0 = kt*64 + nt*8 + c*2;
            if (col0     > qg0) sf[nt][0] = -1e30f;
            if (col0 + 1 > qg0) sf[nt][1] = -1e30f;
            if (col0     > qg1) sf[nt][2] = -1e30f;
            if (col0 + 1 > qg1) sf[nt][3] = -1e30f;
        }

        float mx0 = -1e30f, mx1 = -1e30f;
        #pragma unroll
        for (int nt = 0; nt < 8; nt++) {
            mx0 = fmaxf(mx0, fmaxf(sf[nt][0], sf[nt][1]));
            mx1 = fmaxf(mx1, fmaxf(sf[nt][2], sf[nt][3]));
        }
        mx0 = fmaxf(mx0, __shfl_xor_sync(0xffffffffu, mx0, 1));
        mx0 = fmaxf(mx0, __shfl_xor_sync(0xffffffffu, mx0, 2));
        mx1 = fmaxf(mx1, __shfl_xor_sync(0xffffffffu, mx1, 1));
        mx1 = fmaxf(mx1, __shfl_xor_sync(0xffffffffu, mx1, 2));

        const float mn0 = fmaxf(m0i, mx0);
        const float mn1 = fmaxf(m1i, mx1);
        const float cor0 = __expf(m0i - mn0);
        const float cor1 = __expf(m1i - mn1);

        float s0 = 0.f, s1 = 0.f;
        #pragma unroll
        for (int nt = 0; nt < 8; nt++) {
            const float p00 = __expf(sf[nt][0] - mn0);
            const float p01 = __expf(sf[nt][1] - mn0);
            const float p10 = __expf(sf[nt][2] - mn1);
            const float p11 = __expf(sf[nt][3] - mn1);
            s0 += p00 + p01;
            s1 += p10 + p11;
            Ps[warp*16 + r    ][nt*4 + c] = f2h2(p00, p01);
            Ps[warp*16 + r + 8][nt*4 + c] = f2h2(p10, p11);
        }
        s0 += __shfl_xor_sync(0xffffffffu, s0, 1);
        s0 += __shfl_xor_sync(0xffffffffu, s0, 2);
        s1 += __shfl_xor_sync(0xffffffffu, s1, 1);
        s1 += __shfl_xor_sync(0xffffffffu, s1, 2);

        l0i = l0i * cor0 + s0;
        l1i = l1i * cor1 + s1;
        m0i = mn0;
        m1i = mn1;

        #pragma unroll
        for (int nt = 0; nt < 8; nt++) {
            of[nt][0] *= cor0;
            of[nt][1] *= cor0;
            of[nt][2] *= cor1;
            of[nt][3] *= cor1;
        }

        __syncwarp();

        #pragma unroll
        for (int kk = 0; kk < 4; kk++) {
            uint32_t af[4];
            af[0] = Ps[warp*16 + r    ][kk*8 + c    ];
            af[1] = Ps[warp*16 + r + 8][kk*8 + c    ];
            af[2] = Ps[warp*16 + r    ][kk*8 + c + 4];
            af[3] = Ps[warp*16 + r + 8][kk*8 + c + 4];
            #pragma unroll
            for (int nt = 0; nt < 8; nt++) {
                uint32_t bf[2];
                bf[0] = Vs[kk*8 + c    ][nt*8 + r];
                bf[1] = Vs[kk*8 + c + 4][nt*8 + r];
                mma_f16(of[nt], af, bf, of[nt]);
            }
        }
    }

    const int b = bh >> 4, h = bh & 15;
    const float inv0 = 1.0f / l0i;
    const float inv1 = 1.0f / l1i;
    const int qg0 = qbase + r;
    #pragma unroll
    for (int nt = 0; nt < 8; nt++) {
        const int d = nt*8 + c*2;
        *reinterpret_cast<uint32_t*>(
            g_ctx + ((size_t)(b*SS + qg0    ))*DD + h*HDIM + d) = f2h2(of[nt][0]*inv0, of[nt][1]*inv0);
        *reinterpret_cast<uint32_t*>(
            g_ctx + ((size_t)(b*SS + qg0 + 8))*DD + h*HDIM + d) = f2h2(of[nt][2]*inv1, of[nt][3]*inv1);
    }
}

// ---------------------------------------------------------------------------
// Launch
// ---------------------------------------------------------------------------
extern "C" void kernel_launch(void* const* d_in, const int* in_sizes, int n_in,
                              void* d_out, int out_size)
{
    const float* x  = (const float*)d_in[0];
    const float* Wq = (const float*)d_in[1];
    const float* Wk = (const float*)d_in[2];
    const float* Wv = (const float*)d_in[3];
    const float* Wo = (const float*)d_in[4];
    const float* bo = (const float*)d_in[5];
    float* out = (float*)d_out;

    (void)in_sizes; (void)n_in; (void)out_size;

    __half* dx;  cudaGetSymbolAddress((void**)&dx,  g_x16);
    __half* dwq; cudaGetSymbolAddress((void**)&dwq, g_wq16);
    __half* dwk; cudaGetSymbolAddress((void**)&dwk, g_wk16);
    __half* dwv; cudaGetSymbolAddress((void**)&dwv, g_wv16);
    __half* dwo; cudaGetSymbolAddress((void**)&dwo, g_wo16);

    const int nx4 = NTOK*DD/4;   // 1M
    const int nw4 = DD*DD/4;     // 256K
    cvt_kernel<<<nx4/256, 256>>>((const float4*)x,  (uint2*)dx,  nx4);
    cvt_kernel<<<nw4/256, 256>>>((const float4*)Wq, (uint2*)dwq, nw4);
    cvt_kernel<<<nw4/256, 256>>>((const float4*)Wk, (uint2*)dwk, nw4);
    cvt_kernel<<<nw4/256, 256>>>((const float4*)Wv, (uint2*)dwv, nw4);
    cvt_kernel<<<nw4/256, 256>>>((const float4*)Wo, (uint2*)dwo, nw4);

    qkv_gemm_kernel<<<dim3(8, 32, 3), 256>>>();
    attn_kernel<<<dim3(16, 32), 256>>>();
    oproj_kernel<<<dim3(8, 32), 256>>>(bo, out);
}

// round 7
// speedup vs baseline: 6.2462x; 1.2144x over previous
#include <cuda_runtime.h>
#include <cuda_fp16.h>
#include <math.h>
#include <stdint.h>

#define BB   2
#define SS   2048
#define DD   1024
#define NH   16
#define HDIM 64
#define NTOK (BB*SS)

// Scratch (device globals: allocation-free per harness rules)
__device__ __half g_q[NTOK*DD];    // [b][h][s][d], pre-scaled by 0.125
__device__ __half g_k[NTOK*DD];
__device__ __half g_v[NTOK*DD];
__device__ __half g_ctx[NTOK*DD];  // [b][s][h*64+d]
__device__ __half g_x16[NTOK*DD];  // fp16 copy of x
__device__ __half g_wq16[DD*DD];
__device__ __half g_wk16[DD*DD];
__device__ __half g_wv16[DD*DD];
__device__ __half g_wo16[DD*DD];

// ---------------------------------------------------------------------------
// Helpers
// ---------------------------------------------------------------------------
__device__ __forceinline__ uint32_t smem_u32(const void* p) {
    uint32_t a;
    asm("{ .reg .u64 t; cvta.to.shared.u64 t, %1; cvt.u32.u64 %0, t; }"
        : "=r"(a) : "l"(p));
    return a;
}
__device__ __forceinline__ uint32_t f2h2(float lo, float hi) {
    __half2 h = __floats2half2_rn(lo, hi);
    return *reinterpret_cast<uint32_t*>(&h);
}
__device__ __forceinline__ void mma_f16(float d[4], const uint32_t a[4],
                                        const uint32_t* b, const float c[4]) {
    asm volatile(
        "mma.sync.aligned.m16n8k16.row.col.f32.f16.f16.f32 "
        "{%0,%1,%2,%3}, {%4,%5,%6,%7}, {%8,%9}, {%10,%11,%12,%13};"
        : "=f"(d[0]), "=f"(d[1]), "=f"(d[2]), "=f"(d[3])
        : "r"(a[0]), "r"(a[1]), "r"(a[2]), "r"(a[3]),
          "r"(b[0]), "r"(b[1]),
          "f"(c[0]), "f"(c[1]), "f"(c[2]), "f"(c[3]));
}
__device__ __forceinline__ void ldsm_x4(uint32_t r[4], uint32_t addr) {
    asm volatile("ldmatrix.sync.aligned.m8n8.x4.shared.b16 {%0,%1,%2,%3}, [%4];"
        : "=r"(r[0]), "=r"(r[1]), "=r"(r[2]), "=r"(r[3]) : "r"(addr));
}
__device__ __forceinline__ void ldsm_x4_t(uint32_t r[4], uint32_t addr) {
    asm volatile("ldmatrix.sync.aligned.m8n8.x4.trans.shared.b16 {%0,%1,%2,%3}, [%4];"
        : "=r"(r[0]), "=r"(r[1]), "=r"(r[2]), "=r"(r[3]) : "r"(addr));
}
__device__ __forceinline__ void cp_async16(uint32_t saddr, const void* gaddr) {
    asm volatile("cp.async.cg.shared.global [%0], [%1], 16;"
        :: "r"(saddr), "l"(gaddr) : "memory");
}

// ---------------------------------------------------------------------------
// Kernel 0: fp32 -> fp16 convert (grid-stride over float4)
// ---------------------------------------------------------------------------
__global__ __launch_bounds__(256) void cvt_kernel(const float4* __restrict__ src,
                                                  uint2* __restrict__ dst, int n4)
{
    const int i = blockIdx.x * 256 + threadIdx.x;
    if (i < n4) {
        const float4 v = src[i];
        uint2 o;
        o.x = f2h2(v.x, v.y);
        o.y = f2h2(v.z, v.w);
        dst[i] = o;
    }
}

// ---------------------------------------------------------------------------
// fp16 GEMM core (unchanged from round 6 — passing)
// ---------------------------------------------------------------------------
#define GSTG 16384u

__device__ __forceinline__ void gemm16_stage(
    const __half* __restrict__ A, const __half* __restrict__ B,
    int m0, int n0, uint32_t sbase, int s, int k0, int tid)
{
    #pragma unroll
    for (int j = 0; j < 2; j++) {
        const int id  = tid + j*256;
        const int row = id >> 2;
        const int ch  = id & 3;
        const uint32_t sw = (uint32_t)(row*64 + ((ch ^ ((row>>1)&3))*16));
        cp_async16(sbase + (uint32_t)s*GSTG + sw,
                   A + (size_t)(m0 + row)*DD + k0 + ch*8);
        cp_async16(sbase + (uint32_t)s*GSTG + 8192u + sw,
                   B + (size_t)(n0 + row)*DD + k0 + ch*8);
    }
    asm volatile("cp.async.commit_group;" ::: "memory");
}

__device__ __forceinline__ void gemm16_core(
    const __half* __restrict__ A, const __half* __restrict__ B,
    int m0, int n0, uint32_t sbase, float acc[4][4][4])
{
    const int tid  = threadIdx.x;
    const int lane = tid & 31;
    const int warp = tid >> 5;
    const int wm = warp >> 2;
    const int wn = warp & 3;

    const int a_row_off = (lane & 7) + ((lane >> 3) & 1) * 8;
    const int a_ch_off  = lane >> 4;
    const int b_row_off = ((lane >> 4) << 3) + (lane & 7);
    const int b_ch_off  = (lane >> 3) & 1;

    gemm16_stage(A, B, m0, n0, sbase, 0, 0, tid);
    gemm16_stage(A, B, m0, n0, sbase, 1, 32, tid);

    for (int i = 0; i < 32; i++) {
        const int s = i - (i/3)*3;
        if (i >= 30) { asm volatile("cp.async.wait_group 0;" ::: "memory"); }
        else         { asm volatile("cp.async.wait_group 1;" ::: "memory"); }
        __syncthreads();

        if (i + 2 < 32) {
            const int s2 = (i+2) - ((i+2)/3)*3;
            gemm16_stage(A, B, m0, n0, sbase, s2, (i+2)*32, tid);
        }

        const uint32_t sA = sbase + (uint32_t)s*GSTG;
        const uint32_t sB = sA + 8192u;

        #pragma unroll
        for (int ks = 0; ks < 2; ks++) {
            uint32_t af[4][4];
            #pragma unroll
            for (int mt = 0; mt < 4; mt++) {
                const int row = wm*64 + mt*16 + a_row_off;
                const int ch  = 2*ks + a_ch_off;
                ldsm_x4(af[mt], sA + (uint32_t)(row*64 + ((ch ^ ((row>>1)&3))*16)));
            }
            uint32_t bf[4][2];
            #pragma unroll
            for (int pr = 0; pr < 2; pr++) {
                const int row = wn*32 + pr*16 + b_row_off;
                const int ch  = 2*ks + b_ch_off;
                uint32_t t[4];
                ldsm_x4(t, sB + (uint32_t)(row*64 + ((ch ^ ((row>>1)&3))*16)));
                bf[pr*2  ][0] = t[0]; bf[pr*2  ][1] = t[1];
                bf[pr*2+1][0] = t[2]; bf[pr*2+1][1] = t[3];
            }
            #pragma unroll
            for (int mt = 0; mt < 4; mt++)
                #pragma unroll
                for (int nt = 0; nt < 4; nt++)
                    mma_f16(acc[mt][nt], af[mt], bf[nt], acc[mt][nt]);
        }
    }
}

// ---------------------------------------------------------------------------
// Kernel 1: fused QKV projection. grid (8, 32, 3), block 256. fp16 in/out.
// ---------------------------------------------------------------------------
__global__ __launch_bounds__(256) void qkv_gemm_kernel()
{
    __shared__ __align__(16) char smg[3*GSTG];
    const uint32_t sbase = smem_u32(smg);

    const __half* W   = (blockIdx.z == 0) ? g_wq16 : (blockIdx.z == 1) ? g_wk16 : g_wv16;
    __half*       out = (blockIdx.z == 0) ? g_q    : (blockIdx.z == 1) ? g_k    : g_v;
    const float oscale = (blockIdx.z == 0) ? 0.125f : 1.0f;

    const int m0 = blockIdx.y * 128;
    const int n0 = blockIdx.x * 128;

    float acc[4][4][4];
    #pragma unroll
    for (int i = 0; i < 4; i++)
        #pragma unroll
        for (int j = 0; j < 4; j++)
            #pragma unroll
            for (int k = 0; k < 4; k++) acc[i][j][k] = 0.f;

    gemm16_core(g_x16, W, m0, n0, sbase, acc);

    const int lane = threadIdx.x & 31;
    const int warp = threadIdx.x >> 5;
    const int wm = warp >> 2, wn = warp & 3;
    const int r = lane >> 2, c = lane & 3;

    #pragma unroll
    for (int mt = 0; mt < 4; mt++) {
        #pragma unroll
        for (int nt = 0; nt < 4; nt++) {
            #pragma unroll
            for (int half = 0; half < 2; half++) {
                const int m = m0 + wm*64 + mt*16 + r + half*8;
                const int b = m >> 11;
                const int s = m & 2047;
                const int n = n0 + wn*32 + nt*8 + c*2;
                const int h = n >> 6;
                const int d = n & 63;
                const uint32_t v = f2h2(acc[mt][nt][half*2+0]*oscale,
                                        acc[mt][nt][half*2+1]*oscale);
                *reinterpret_cast<uint32_t*>(
                    out + (((size_t)(b*NH + h))*SS + s)*HDIM + d) = v;
            }
        }
    }
}

// ---------------------------------------------------------------------------
// Kernel 3: output projection + bias. grid (8, 32), block 256.
// ---------------------------------------------------------------------------
__global__ __launch_bounds__(256) void oproj_kernel(
    const float* __restrict__ bo,
    float* __restrict__ out)
{
    __shared__ __align__(16) char smg[3*GSTG];
    const uint32_t sbase = smem_u32(smg);

    const int m0 = blockIdx.y * 128;
    const int n0 = blockIdx.x * 128;

    float acc[4][4][4];
    #pragma unroll
    for (int i = 0; i < 4; i++)
        #pragma unroll
        for (int j = 0; j < 4; j++)
            #pragma unroll
            for (int k = 0; k < 4; k++) acc[i][j][k] = 0.f;

    gemm16_core(g_ctx, g_wo16, m0, n0, sbase, acc);

    const int lane = threadIdx.x & 31;
    const int warp = threadIdx.x >> 5;
    const int wm = warp >> 2, wn = warp & 3;
    const int r = lane >> 2, c = lane & 3;

    #pragma unroll
    for (int mt = 0; mt < 4; mt++) {
        #pragma unroll
        for (int nt = 0; nt < 4; nt++) {
            #pragma unroll
            for (int half = 0; half < 2; half++) {
                const int m = m0 + wm*64 + mt*16 + r + half*8;
                const int n = n0 + wn*32 + nt*8 + c*2;
                float* o = out + (size_t)m*DD + n;
                o[0] = acc[mt][nt][half*2 + 0] + bo[n];
                o[1] = acc[mt][nt][half*2 + 1] + bo[n + 1];
            }
        }
    }
}

// ---------------------------------------------------------------------------
// Kernel 2: causal flash attention, fp16 mma, cp.async KV pipeline,
// ldmatrix K/V fragments, P kept in registers.
// grid (16 q-tiles, 32 bh), block 256 (8 warps, 16 q-rows/warp), KV tile 64.
// Smem: 2 stages x (K 8KB + V 8KB) = 32KB. K/V tile layout: [key(64)][d(64)]h,
// 128B rows, swizzle: byte = key*128 + ((ch ^ (key&7))*16), ch = d>>3.
// ---------------------------------------------------------------------------
#define ASTG 16384u

__global__ __launch_bounds__(256) void attn_kernel()
{
    __shared__ __align__(16) char smA[2*ASTG];
    const uint32_t sbase = smem_u32(smA);

    const int tid  = threadIdx.x;
    const int lane = tid & 31;
    const int warp = tid >> 5;
    const int r = lane >> 2;
    const int c = lane & 3;
    const int qt = blockIdx.x;
    const int bh = blockIdx.y;

    const __half* Qg = g_q + (size_t)bh * SS * HDIM;
    const __half* Kg = g_k + (size_t)bh * SS * HDIM;
    const __half* Vg = g_v + (size_t)bh * SS * HDIM;
    const uint32_t* Qg2 = reinterpret_cast<const uint32_t*>(Qg);
    const int q0 = qt * 128;
    const int qbase = q0 + warp * 16;

    // Q fragments (g_q pre-scaled by 0.125)
    uint32_t qf[4][4];
    #pragma unroll
    for (int kk = 0; kk < 4; kk++) {
        qf[kk][0] = Qg2[(size_t)(qbase + r    )*32 + kk*8 + c    ];
        qf[kk][1] = Qg2[(size_t)(qbase + r + 8)*32 + kk*8 + c    ];
        qf[kk][2] = Qg2[(size_t)(qbase + r    )*32 + kk*8 + c + 4];
        qf[kk][3] = Qg2[(size_t)(qbase + r + 8)*32 + kk*8 + c + 4];
    }

    // ldmatrix lane-offsets
    const int k_key_off = ((lane >> 4) & 1) * 8 + (lane & 7);  // + ntp*16
    const int k_ch_off  = (lane >> 3) & 1;                     // + 2*kk
    const int v_key_off = ((lane >> 3) & 1) * 8 + (lane & 7);  // + 16*kk
    const int v_ch_off  = (lane >> 4);                         // + 2*ntp

    float of[8][4];
    #pragma unroll
    for (int nt = 0; nt < 8; nt++)
        #pragma unroll
        for (int j = 0; j < 4; j++) of[nt][j] = 0.f;
    float m0i = -1e30f, m1i = -1e30f, l0i = 0.f, l1i = 0.f;

    // stage KV tile kt into buffer s
    auto stage = [&](int kt, int s) {
        const uint32_t sb = sbase + (uint32_t)s * ASTG;
        #pragma unroll
        for (int j = 0; j < 2; j++) {
            const int id  = tid + j*256;
            const int row = id >> 3;
            const int ch  = id & 7;
            const uint32_t sw = (uint32_t)(row*128 + ((ch ^ (row & 7))*16));
            cp_async16(sb + sw,          Kg + (size_t)(kt*64 + row)*HDIM + ch*8);
            cp_async16(sb + 8192u + sw,  Vg + (size_t)(kt*64 + row)*HDIM + ch*8);
        }
        asm volatile("cp.async.commit_group;" ::: "memory");
    };

    const int ktmax = 2*qt + 1;
    stage(0, 0);

    for (int kt = 0; kt <= ktmax; kt++) {
        asm volatile("cp.async.wait_group 0;" ::: "memory");
        __syncthreads();   // data visible; previous compute on other buffer done
        if (kt < ktmax) stage(kt + 1, (kt + 1) & 1);

        if (kt*64 > qbase + 15) continue;   // causal early-exit (syncs stay at loop top)

        const uint32_t sK = sbase + (uint32_t)(kt & 1) * ASTG;
        const uint32_t sV = sK + 8192u;

        // ---- S = Q @ K^T ----
        float sf[8][4];
        #pragma unroll
        for (int nt = 0; nt < 8; nt++)
            #pragma unroll
            for (int j = 0; j < 4; j++) sf[nt][j] = 0.f;

        #pragma unroll
        for (int kk = 0; kk < 4; kk++) {
            #pragma unroll
            for (int ntp = 0; ntp < 4; ntp++) {
                const int key = ntp*16 + k_key_off;
                const int ch  = 2*kk + k_ch_off;
                uint32_t t[4];
                ldsm_x4(t, sK + (uint32_t)(key*128 + ((ch ^ (key & 7))*16)));
                mma_f16(sf[2*ntp    ], qf[kk], &t[0], sf[2*ntp    ]);
                mma_f16(sf[2*ntp + 1], qf[kk], &t[2], sf[2*ntp + 1]);
            }
        }

        // ---- mask + online softmax ----
        const int qg0 = qbase + r;
        const int qg1 = qg0 + 8;
        #pragma unroll
        for (int nt = 0; nt < 8; nt++) {
            const int col0 = kt*64 + nt*8 + c*2;
            if (col0     > qg0) sf[nt][0] = -1e30f;
            if (col0 + 1 > qg0) sf[nt][1] = -1e30f;
            if (col0     > qg1) sf[nt][2] = -1e30f;
            if (col0 + 1 > qg1) sf[nt][3] = -1e30f;
        }

        float mx0 = -1e30f, mx1 = -1e30f;
        #pragma unroll
        for (int nt = 0; nt < 8; nt++) {
            mx0 = fmaxf(mx0, fmaxf(sf[nt][0], sf[nt][1]));
            mx1 = fmaxf(mx1, fmaxf(sf[nt][2], sf[nt][3]));
        }
        mx0 = fmaxf(mx0, __shfl_xor_sync(0xffffffffu, mx0, 1));
        mx0 = fmaxf(mx0, __shfl_xor_sync(0xffffffffu, mx0, 2));
        mx1 = fmaxf(mx1, __shfl_xor_sync(0xffffffffu, mx1, 1));
        mx1 = fmaxf(mx1, __shfl_xor_sync(0xffffffffu, mx1, 2));

        const float mn0 = fmaxf(m0i, mx0);
        const float mn1 = fmaxf(m1i, mx1);
        const float cor0 = __expf(m0i - mn0);
        const float cor1 = __expf(m1i - mn1);

        // exp + pack P directly into A-fragments: pk[kk] covers keys 16kk..+15
        uint32_t pk[4][4];
        float s0 = 0.f, s1 = 0.f;
        #pragma unroll
        for (int nt = 0; nt < 8; nt++) {
            const float p00 = __expf(sf[nt][0] - mn0);
            const float p01 = __expf(sf[nt][1] - mn0);
            const float p10 = __expf(sf[nt][2] - mn1);
            const float p11 = __expf(sf[nt][3] - mn1);
            s0 += p00 + p01;
            s1 += p10 + p11;
            pk[nt >> 1][(nt & 1)*2    ] = f2h2(p00, p01);
            pk[nt >> 1][(nt & 1)*2 + 1] = f2h2(p10, p11);
        }
        s0 += __shfl_xor_sync(0xffffffffu, s0, 1);
        s0 += __shfl_xor_sync(0xffffffffu, s0, 2);
        s1 += __shfl_xor_sync(0xffffffffu, s1, 1);
        s1 += __shfl_xor_sync(0xffffffffu, s1, 2);

        l0i = l0i * cor0 + s0;
        l1i = l1i * cor1 + s1;
        m0i = mn0;
        m1i = mn1;

        #pragma unroll
        for (int nt = 0; nt < 8; nt++) {
            of[nt][0] *= cor0;
            of[nt][1] *= cor0;
            of[nt][2] *= cor1;
            of[nt][3] *= cor1;
        }

        // ---- O += P @ V ---- (V B-frags via ldmatrix.trans on [key][d])
        #pragma unroll
        for (int kk = 0; kk < 4; kk++) {
            #pragma unroll
            for (int ntp = 0; ntp < 4; ntp++) {
                const int key = 16*kk + v_key_off;
                const int ch  = 2*ntp + v_ch_off;
                uint32_t t[4];
                ldsm_x4_t(t, sV + (uint32_t)(key*128 + ((ch ^ (key & 7))*16)));
                mma_f16(of[2*ntp    ], pk[kk], &t[0], of[2*ntp    ]);
                mma_f16(of[2*ntp + 1], pk[kk], &t[2], of[2*ntp + 1]);
            }
        }
    }

    // epilogue: normalize, write ctx (fp16) [b][s][h*64+d]
    const int b = bh >> 4, h = bh & 15;
    const float inv0 = 1.0f / l0i;
    const float inv1 = 1.0f / l1i;
    const int qg0 = qbase + r;
    #pragma unroll
    for (int nt = 0; nt < 8; nt++) {
        const int d = nt*8 + c*2;
        *reinterpret_cast<uint32_t*>(
            g_ctx + ((size_t)(b*SS + qg0    ))*DD + h*HDIM + d) = f2h2(of[nt][0]*inv0, of[nt][1]*inv0);
        *reinterpret_cast<uint32_t*>(
            g_ctx + ((size_t)(b*SS + qg0 + 8))*DD + h*HDIM + d) = f2h2(of[nt][2]*inv1, of[nt][3]*inv1);
    }
}

// ---------------------------------------------------------------------------
// Launch
// ---------------------------------------------------------------------------
extern "C" void kernel_launch(void* const* d_in, const int* in_sizes, int n_in,
                              void* d_out, int out_size)
{
    const float* x  = (const float*)d_in[0];
    const float* Wq = (const float*)d_in[1];
    const float* Wk = (const float*)d_in[2];
    const float* Wv = (const float*)d_in[3];
    const float* Wo = (const float*)d_in[4];
    const float* bo = (const float*)d_in[5];
    float* out = (float*)d_out;

    (void)in_sizes; (void)n_in; (void)out_size;

    __half* dx;  cudaGetSymbolAddress((void**)&dx,  g_x16);
    __half* dwq; cudaGetSymbolAddress((void**)&dwq, g_wq16);
    __half* dwk; cudaGetSymbolAddress((void**)&dwk, g_wk16);
    __half* dwv; cudaGetSymbolAddress((void**)&dwv, g_wv16);
    __half* dwo; cudaGetSymbolAddress((void**)&dwo, g_wo16);

    const int nx4 = NTOK*DD/4;   // 1M
    const int nw4 = DD*DD/4;     // 256K
    cvt_kernel<<<nx4/256, 256>>>((const float4*)x,  (uint2*)dx,  nx4);
    cvt_kernel<<<nw4/256, 256>>>((const float4*)Wq, (uint2*)dwq, nw4);
    cvt_kernel<<<nw4/256, 256>>>((const float4*)Wk, (uint2*)dwk, nw4);
    cvt_kernel<<<nw4/256, 256>>>((const float4*)Wv, (uint2*)dwv, nw4);
    cvt_kernel<<<nw4/256, 256>>>((const float4*)Wo, (uint2*)dwo, nw4);

    qkv_gemm_kernel<<<dim3(8, 32, 3), 256>>>();
    attn_kernel<<<dim3(16, 32), 256>>>();
    oproj_kernel<<<dim3(8, 32), 256>>>(bo, out);
}

// round 8
// speedup vs baseline: 6.6876x; 1.0707x over previous
#include <cuda_runtime.h>
#include <cuda_fp16.h>
#include <math.h>
#include <stdint.h>

#define BB   2
#define SS   2048
#define DD   1024
#define NH   16
#define HDIM 64
#define NTOK (BB*SS)

// Scratch (device globals: allocation-free per harness rules)
__device__ __half g_q[NTOK*DD];    // [b][h][s][d], pre-scaled by 0.125*log2(e)
__device__ __half g_k[NTOK*DD];
__device__ __half g_v[NTOK*DD];
__device__ __half g_ctx[NTOK*DD];  // [b][s][h*64+d]
__device__ __half g_x16[NTOK*DD];  // fp16 copy of x
__device__ __half g_wq16[DD*DD];
__device__ __half g_wk16[DD*DD];
__device__ __half g_wv16[DD*DD];
__device__ __half g_wo16[DD*DD];

// ---------------------------------------------------------------------------
// Helpers
// ---------------------------------------------------------------------------
__device__ __forceinline__ uint32_t smem_u32(const void* p) {
    uint32_t a;
    asm("{ .reg .u64 t; cvta.to.shared.u64 t, %1; cvt.u32.u64 %0, t; }"
        : "=r"(a) : "l"(p));
    return a;
}
__device__ __forceinline__ uint32_t f2h2(float lo, float hi) {
    __half2 h = __floats2half2_rn(lo, hi);
    return *reinterpret_cast<uint32_t*>(&h);
}
__device__ __forceinline__ void mma_f16(float d[4], const uint32_t a[4],
                                        const uint32_t* b, const float c[4]) {
    asm volatile(
        "mma.sync.aligned.m16n8k16.row.col.f32.f16.f16.f32 "
        "{%0,%1,%2,%3}, {%4,%5,%6,%7}, {%8,%9}, {%10,%11,%12,%13};"
        : "=f"(d[0]), "=f"(d[1]), "=f"(d[2]), "=f"(d[3])
        : "r"(a[0]), "r"(a[1]), "r"(a[2]), "r"(a[3]),
          "r"(b[0]), "r"(b[1]),
          "f"(c[0]), "f"(c[1]), "f"(c[2]), "f"(c[3]));
}
__device__ __forceinline__ void ldsm_x4(uint32_t r[4], uint32_t addr) {
    asm volatile("ldmatrix.sync.aligned.m8n8.x4.shared.b16 {%0,%1,%2,%3}, [%4];"
        : "=r"(r[0]), "=r"(r[1]), "=r"(r[2]), "=r"(r[3]) : "r"(addr));
}
__device__ __forceinline__ void ldsm_x4_t(uint32_t r[4], uint32_t addr) {
    asm volatile("ldmatrix.sync.aligned.m8n8.x4.trans.shared.b16 {%0,%1,%2,%3}, [%4];"
        : "=r"(r[0]), "=r"(r[1]), "=r"(r[2]), "=r"(r[3]) : "r"(addr));
}
__device__ __forceinline__ void cp_async16(uint32_t saddr, const void* gaddr) {
    asm volatile("cp.async.cg.shared.global [%0], [%1], 16;"
        :: "r"(saddr), "l"(gaddr) : "memory");
}

// ---------------------------------------------------------------------------
// Kernel 0a/0b: fp32 -> fp16 converts
// ---------------------------------------------------------------------------
__global__ __launch_bounds__(256) void cvt_x_kernel(const float4* __restrict__ src,
                                                    uint2* __restrict__ dst, int n4)
{
    const int i = blockIdx.x * 256 + threadIdx.x;
    if (i < n4) {
        const float4 v = src[i];
        uint2 o;
        o.x = f2h2(v.x, v.y);
        o.y = f2h2(v.z, v.w);
        dst[i] = o;
    }
}

__global__ __launch_bounds__(256) void cvt_w_kernel(
    const float4* __restrict__ w0, const float4* __restrict__ w1,
    const float4* __restrict__ w2, const float4* __restrict__ w3,
    uint2* __restrict__ d0, uint2* __restrict__ d1,
    uint2* __restrict__ d2, uint2* __restrict__ d3)
{
    const int i = blockIdx.x * 256 + threadIdx.x;   // < DD*DD/4
    const float4* s = (blockIdx.y == 0) ? w0 : (blockIdx.y == 1) ? w1
                    : (blockIdx.y == 2) ? w2 : w3;
    uint2* d = (blockIdx.y == 0) ? d0 : (blockIdx.y == 1) ? d1
             : (blockIdx.y == 2) ? d2 : d3;
    const float4 v = s[i];
    uint2 o;
    o.x = f2h2(v.x, v.y);
    o.y = f2h2(v.z, v.w);
    d[i] = o;
}

// ---------------------------------------------------------------------------
// fp16 GEMM core: C(128x256) = A[m0:+128,:] @ B[n0:+256,:]^T, K=1024.
// 256 thr = 8 warps (2x4), warp tile 64x64, BK=32, 3-stage cp.async pipeline.
// Smem/stage 24KB: A 128x32h at +0 (8KB), B 256x32h at +8192 (16KB).
// Swizzle: byte = row*64 + ((ch ^ ((row>>1)&3))*16), ch = k>>3.
// ---------------------------------------------------------------------------
#define GSTG 24576u

__device__ __forceinline__ void gemm16_stage(
    const __half* __restrict__ A, const __half* __restrict__ B,
    int m0, int n0, uint32_t sbase, int s, int k0, int tid)
{
    const uint32_t sb = sbase + (uint32_t)s*GSTG;
    #pragma unroll
    for (int j = 0; j < 2; j++) {
        const int id  = tid + j*256;
        const int row = id >> 2;
        const int ch  = id & 3;
        const uint32_t sw = (uint32_t)(row*64 + ((ch ^ ((row>>1)&3))*16));
        cp_async16(sb + sw, A + (size_t)(m0 + row)*DD + k0 + ch*8);
    }
    #pragma unroll
    for (int j = 0; j < 4; j++) {
        const int id  = tid + j*256;
        const int row = id >> 2;
        const int ch  = id & 3;
        const uint32_t sw = (uint32_t)(row*64 + ((ch ^ ((row>>1)&3))*16));
        cp_async16(sb + 8192u + sw, B + (size_t)(n0 + row)*DD + k0 + ch*8);
    }
    asm volatile("cp.async.commit_group;" ::: "memory");
}

__device__ __forceinline__ void gemm16_core(
    const __half* __restrict__ A, const __half* __restrict__ B,
    int m0, int n0, uint32_t sbase, float acc[4][8][4])
{
    const int tid  = threadIdx.x;
    const int lane = tid & 31;
    const int warp = tid >> 5;
    const int wm = warp >> 2;        // 0..1 (64 m-rows)
    const int wn = warp & 3;         // 0..3 (64 n-cols)

    const int a_row_off = (lane & 7) + ((lane >> 3) & 1) * 8;
    const int a_ch_off  = lane >> 4;
    const int b_row_off = ((lane >> 4) << 3) + (lane & 7);
    const int b_ch_off  = (lane >> 3) & 1;

    gemm16_stage(A, B, m0, n0, sbase, 0, 0, tid);
    gemm16_stage(A, B, m0, n0, sbase, 1, 32, tid);

    for (int i = 0; i < 32; i++) {
        const int s = i - (i/3)*3;
        if (i >= 30) { asm volatile("cp.async.wait_group 0;" ::: "memory"); }
        else         { asm volatile("cp.async.wait_group 1;" ::: "memory"); }
        __syncthreads();

        if (i + 2 < 32) {
            const int s2 = (i+2) - ((i+2)/3)*3;
            gemm16_stage(A, B, m0, n0, sbase, s2, (i+2)*32, tid);
        }

        const uint32_t sA = sbase + (uint32_t)s*GSTG;
        const uint32_t sB = sA + 8192u;

        #pragma unroll
        for (int ks = 0; ks < 2; ks++) {
            uint32_t af[4][4];
            #pragma unroll
            for (int mt = 0; mt < 4; mt++) {
                const int row = wm*64 + mt*16 + a_row_off;
                const int ch  = 2*ks + a_ch_off;
                ldsm_x4(af[mt], sA + (uint32_t)(row*64 + ((ch ^ ((row>>1)&3))*16)));
            }
            uint32_t bf[8][2];
            #pragma unroll
            for (int pr = 0; pr < 4; pr++) {
                const int row = wn*64 + pr*16 + b_row_off;
                const int ch  = 2*ks + b_ch_off;
                uint32_t t[4];
                ldsm_x4(t, sB + (uint32_t)(row*64 + ((ch ^ ((row>>1)&3))*16)));
                bf[pr*2  ][0] = t[0]; bf[pr*2  ][1] = t[1];
                bf[pr*2+1][0] = t[2]; bf[pr*2+1][1] = t[3];
            }
            #pragma unroll
            for (int mt = 0; mt < 4; mt++)
                #pragma unroll
                for (int nt = 0; nt < 8; nt++)
                    mma_f16(acc[mt][nt], af[mt], bf[nt], acc[mt][nt]);
        }
    }
}

// ---------------------------------------------------------------------------
// Kernel 1: fused QKV projection. grid (4, 32, 3), block 256. fp16 in/out.
// ---------------------------------------------------------------------------
#define QSCALE 0.1803368801111743f   // 0.125 * log2(e)

__global__ __launch_bounds__(256) void qkv_gemm_kernel()
{
    extern __shared__ char smg[];
    const uint32_t sbase = smem_u32(smg);

    const __half* W   = (blockIdx.z == 0) ? g_wq16 : (blockIdx.z == 1) ? g_wk16 : g_wv16;
    __half*       out = (blockIdx.z == 0) ? g_q    : (blockIdx.z == 1) ? g_k    : g_v;
    const float oscale = (blockIdx.z == 0) ? QSCALE : 1.0f;

    const int m0 = blockIdx.y * 128;
    const int n0 = blockIdx.x * 256;

    float acc[4][8][4];
    #pragma unroll
    for (int i = 0; i < 4; i++)
        #pragma unroll
        for (int j = 0; j < 8; j++)
            #pragma unroll
            for (int k = 0; k < 4; k++) acc[i][j][k] = 0.f;

    gemm16_core(g_x16, W, m0, n0, sbase, acc);

    const int lane = threadIdx.x & 31;
    const int warp = threadIdx.x >> 5;
    const int wm = warp >> 2, wn = warp & 3;
    const int r = lane >> 2, c = lane & 3;

    #pragma unroll
    for (int mt = 0; mt < 4; mt++) {
        #pragma unroll
        for (int nt = 0; nt < 8; nt++) {
            #pragma unroll
            for (int half = 0; half < 2; half++) {
                const int m = m0 + wm*64 + mt*16 + r + half*8;
                const int b = m >> 11;
                const int s = m & 2047;
                const int n = n0 + wn*64 + nt*8 + c*2;
                const int h = n >> 6;
                const int d = n & 63;
                const uint32_t v = f2h2(acc[mt][nt][half*2+0]*oscale,
                                        acc[mt][nt][half*2+1]*oscale);
                *reinterpret_cast<uint32_t*>(
                    out + (((size_t)(b*NH + h))*SS + s)*HDIM + d) = v;
            }
        }
    }
}

// ---------------------------------------------------------------------------
// Kernel 3: output projection + bias. grid (4, 32), block 256.
// ---------------------------------------------------------------------------
__global__ __launch_bounds__(256) void oproj_kernel(
    const float* __restrict__ bo,
    float* __restrict__ out)
{
    extern __shared__ char smg[];
    const uint32_t sbase = smem_u32(smg);

    const int m0 = blockIdx.y * 128;
    const int n0 = blockIdx.x * 256;

    float acc[4][8][4];
    #pragma unroll
    for (int i = 0; i < 4; i++)
        #pragma unroll
        for (int j = 0; j < 8; j++)
            #pragma unroll
            for (int k = 0; k < 4; k++) acc[i][j][k] = 0.f;

    gemm16_core(g_ctx, g_wo16, m0, n0, sbase, acc);

    const int lane = threadIdx.x & 31;
    const int warp = threadIdx.x >> 5;
    const int wm = warp >> 2, wn = warp & 3;
    const int r = lane >> 2, c = lane & 3;

    #pragma unroll
    for (int mt = 0; mt < 4; mt++) {
        #pragma unroll
        for (int nt = 0; nt < 8; nt++) {
            #pragma unroll
            for (int half = 0; half < 2; half++) {
                const int m = m0 + wm*64 + mt*16 + r + half*8;
                const int n = n0 + wn*64 + nt*8 + c*2;
                float* o = out + (size_t)m*DD + n;
                o[0] = acc[mt][nt][half*2 + 0] + bo[n];
                o[1] = acc[mt][nt][half*2 + 1] + bo[n + 1];
            }
        }
    }
}

// ---------------------------------------------------------------------------
// Kernel 2: causal flash attention (log2-domain softmax, reversed qt order).
// grid (16 q-tiles, 32 bh), block 256 (8 warps, 16 q-rows/warp), KV tile 64.
// ---------------------------------------------------------------------------
#define ASTG 16384u

__global__ __launch_bounds__(256) void attn_kernel()
{
    __shared__ __align__(16) char smA[2*ASTG];
    const uint32_t sbase = smem_u32(smA);

    const int tid  = threadIdx.x;
    const int lane = tid & 31;
    const int warp = tid >> 5;
    const int r = lane >> 2;
    const int c = lane & 3;
    const int qt = 15 - blockIdx.x;      // heavy CTAs first
    const int bh = blockIdx.y;

    const __half* Qg = g_q + (size_t)bh * SS * HDIM;
    const __half* Kg = g_k + (size_t)bh * SS * HDIM;
    const __half* Vg = g_v + (size_t)bh * SS * HDIM;
    const uint32_t* Qg2 = reinterpret_cast<const uint32_t*>(Qg);
    const int q0 = qt * 128;
    const int qbase = q0 + warp * 16;

    // Q fragments (g_q pre-scaled by 0.125*log2e)
    uint32_t qf[4][4];
    #pragma unroll
    for (int kk = 0; kk < 4; kk++) {
        qf[kk][0] = Qg2[(size_t)(qbase + r    )*32 + kk*8 + c    ];
        qf[kk][1] = Qg2[(size_t)(qbase + r + 8)*32 + kk*8 + c    ];
        qf[kk][2] = Qg2[(size_t)(qbase + r    )*32 + kk*8 + c + 4];
        qf[kk][3] = Qg2[(size_t)(qbase + r + 8)*32 + kk*8 + c + 4];
    }

    const int k_key_off = ((lane >> 4) & 1) * 8 + (lane & 7);
    const int k_ch_off  = (lane >> 3) & 1;
    const int v_key_off = ((lane >> 3) & 1) * 8 + (lane & 7);
    const int v_ch_off  = (lane >> 4);

    float of[8][4];
    #pragma unroll
    for (int nt = 0; nt < 8; nt++)
        #pragma unroll
        for (int j = 0; j < 4; j++) of[nt][j] = 0.f;
    float m0i = -1e30f, m1i = -1e30f, l0i = 0.f, l1i = 0.f;

    auto stage = [&](int kt, int s) {
        const uint32_t sb = sbase + (uint32_t)s * ASTG;
        #pragma unroll
        for (int j = 0; j < 2; j++) {
            const int id  = tid + j*256;
            const int row = id >> 3;
            const int ch  = id & 7;
            const uint32_t sw = (uint32_t)(row*128 + ((ch ^ (row & 7))*16));
            cp_async16(sb + sw,          Kg + (size_t)(kt*64 + row)*HDIM + ch*8);
            cp_async16(sb + 8192u + sw,  Vg + (size_t)(kt*64 + row)*HDIM + ch*8);
        }
        asm volatile("cp.async.commit_group;" ::: "memory");
    };

    const int ktmax = 2*qt + 1;
    stage(0, 0);

    for (int kt = 0; kt <= ktmax; kt++) {
        asm volatile("cp.async.wait_group 0;" ::: "memory");
        __syncthreads();
        if (kt < ktmax) stage(kt + 1, (kt + 1) & 1);

        if (kt*64 > qbase + 15) continue;

        const uint32_t sK = sbase + (uint32_t)(kt & 1) * ASTG;
        const uint32_t sV = sK + 8192u;

        // ---- S = Q @ K^T (log2 domain) ----
        float sf[8][4];
        #pragma unroll
        for (int nt = 0; nt < 8; nt++)
            #pragma unroll
            for (int j = 0; j < 4; j++) sf[nt][j] = 0.f;

        #pragma unroll
        for (int kk = 0; kk < 4; kk++) {
            #pragma unroll
            for (int ntp = 0; ntp < 4; ntp++) {
                const int key = ntp*16 + k_key_off;
                const int ch  = 2*kk + k_ch_off;
                uint32_t t[4];
                ldsm_x4(t, sK + (uint32_t)(key*128 + ((ch ^ (key & 7))*16)));
                mma_f16(sf[2*ntp    ], qf[kk], &t[0], sf[2*ntp    ]);
                mma_f16(sf[2*ntp + 1], qf[kk], &t[2], sf[2*ntp + 1]);
            }
        }

        // ---- causal mask (skip if tile fully visible) ----
        const int qg0 = qbase + r;
        const int qg1 = qg0 + 8;
        if (kt*64 + 63 > qbase) {
            #pragma unroll
            for (int nt = 0; nt < 8; nt++) {
                const int col0 = kt*64 + nt*8 + c*2;
                if (col0     > qg0) sf[nt][0] = -1e30f;
                if (col0 + 1 > qg0) sf[nt][1] = -1e30f;
                if (col0     > qg1) sf[nt][2] = -1e30f;
                if (col0 + 1 > qg1) sf[nt][3] = -1e30f;
            }
        }

        // ---- online softmax (base-2) ----
        float mx0 = -1e30f, mx1 = -1e30f;
        #pragma unroll
        for (int nt = 0; nt < 8; nt++) {
            mx0 = fmaxf(mx0, fmaxf(sf[nt][0], sf[nt][1]));
            mx1 = fmaxf(mx1, fmaxf(sf[nt][2], sf[nt][3]));
        }
        mx0 = fmaxf(mx0, __shfl_xor_sync(0xffffffffu, mx0, 1));
        mx0 = fmaxf(mx0, __shfl_xor_sync(0xffffffffu, mx0, 2));
        mx1 = fmaxf(mx1, __shfl_xor_sync(0xffffffffu, mx1, 1));
        mx1 = fmaxf(mx1, __shfl_xor_sync(0xffffffffu, mx1, 2));

        const float mn0 = fmaxf(m0i, mx0);
        const float mn1 = fmaxf(m1i, mx1);
        const float cor0 = exp2f(m0i - mn0);
        const float cor1 = exp2f(m1i - mn1);

        uint32_t pk[4][4];
        float s0 = 0.f, s1 = 0.f;
        #pragma unroll
        for (int nt = 0; nt < 8; nt++) {
            const float p00 = exp2f(sf[nt][0] - mn0);
            const float p01 = exp2f(sf[nt][1] - mn0);
            const float p10 = exp2f(sf[nt][2] - mn1);
            const float p11 = exp2f(sf[nt][3] - mn1);
            s0 += p00 + p01;
            s1 += p10 + p11;
            pk[nt >> 1][(nt & 1)*2    ] = f2h2(p00, p01);
            pk[nt >> 1][(nt & 1)*2 + 1] = f2h2(p10, p11);
        }
        s0 += __shfl_xor_sync(0xffffffffu, s0, 1);
        s0 += __shfl_xor_sync(0xffffffffu, s0, 2);
        s1 += __shfl_xor_sync(0xffffffffu, s1, 1);
        s1 += __shfl_xor_sync(0xffffffffu, s1, 2);

        l0i = l0i * cor0 + s0;
        l1i = l1i * cor1 + s1;
        m0i = mn0;
        m1i = mn1;

        #pragma unroll
        for (int nt = 0; nt < 8; nt++) {
            of[nt][0] *= cor0;
            of[nt][1] *= cor0;
            of[nt][2] *= cor1;
            of[nt][3] *= cor1;
        }

        // ---- O += P @ V ----
        #pragma unroll
        for (int kk = 0; kk < 4; kk++) {
            #pragma unroll
            for (int ntp = 0; ntp < 4; ntp++) {
                const int key = 16*kk + v_key_off;
                const int ch  = 2*ntp + v_ch_off;
                uint32_t t[4];
                ldsm_x4_t(t, sV + (uint32_t)(key*128 + ((ch ^ (key & 7))*16)));
                mma_f16(of[2*ntp    ], pk[kk], &t[0], of[2*ntp    ]);
                mma_f16(of[2*ntp + 1], pk[kk], &t[2], of[2*ntp + 1]);
            }
        }
    }

    // epilogue: normalize, write ctx (fp16) [b][s][h*64+d]
    const int b = bh >> 4, h = bh & 15;
    const float inv0 = 1.0f / l0i;
    const float inv1 = 1.0f / l1i;
    const int qg0 = qbase + r;
    #pragma unroll
    for (int nt = 0; nt < 8; nt++) {
        const int d = nt*8 + c*2;
        *reinterpret_cast<uint32_t*>(
            g_ctx + ((size_t)(b*SS + qg0    ))*DD + h*HDIM + d) = f2h2(of[nt][0]*inv0, of[nt][1]*inv0);
        *reinterpret_cast<uint32_t*>(
            g_ctx + ((size_t)(b*SS + qg0 + 8))*DD + h*HDIM + d) = f2h2(of[nt][2]*inv1, of[nt][3]*inv1);
    }
}

// ---------------------------------------------------------------------------
// Launch
// ---------------------------------------------------------------------------
extern "C" void kernel_launch(void* const* d_in, const int* in_sizes, int n_in,
                              void* d_out, int out_size)
{
    const float* x  = (const float*)d_in[0];
    const float* Wq = (const float*)d_in[1];
    const float* Wk = (const float*)d_in[2];
    const float* Wv = (const float*)d_in[3];
    const float* Wo = (const float*)d_in[4];
    const float* bo = (const float*)d_in[5];
    float* out = (float*)d_out;

    (void)in_sizes; (void)n_in; (void)out_size;

    __half* dx;  cudaGetSymbolAddress((void**)&dx,  g_x16);
    __half* dwq; cudaGetSymbolAddress((void**)&dwq, g_wq16);
    __half* dwk; cudaGetSymbolAddress((void**)&dwk, g_wk16);
    __half* dwv; cudaGetSymbolAddress((void**)&dwv, g_wv16);
    __half* dwo; cudaGetSymbolAddress((void**)&dwo, g_wo16);

    const int nx4 = NTOK*DD/4;   // 1M
    const int nw4 = DD*DD/4;     // 256K
    cvt_x_kernel<<<nx4/256, 256>>>((const float4*)x, (uint2*)dx, nx4);
    cvt_w_kernel<<<dim3(nw4/256, 4), 256>>>(
        (const float4*)Wq, (const float4*)Wk, (const float4*)Wv, (const float4*)Wo,
        (uint2*)dwq, (uint2*)dwk, (uint2*)dwv, (uint2*)dwo);

    const int gsm = 3 * GSTG;   // 73728 bytes dynamic smem
    cudaFuncSetAttribute(qkv_gemm_kernel,
                         cudaFuncAttributeMaxDynamicSharedMemorySize, gsm);
    cudaFuncSetAttribute(oproj_kernel,
                         cudaFuncAttributeMaxDynamicSharedMemorySize, gsm);

    qkv_gemm_kernel<<<dim3(4, 32, 3), 256, gsm>>>();
    attn_kernel<<<dim3(16, 32), 256>>>();
    oproj_kernel<<<dim3(4, 32), 256, gsm>>>(bo, out);
}

// round 9
// speedup vs baseline: 6.7321x; 1.0067x over previous
#include <cuda_runtime.h>
#include <cuda_fp16.h>
#include <math.h>
#include <stdint.h>

#define BB   2
#define SS   2048
#define DD   1024
#define NH   16
#define HDIM 64
#define NTOK (BB*SS)

// Scratch (device globals: allocation-free per harness rules)
__device__ __half g_q[NTOK*DD];    // [b][h][s][d], pre-scaled by 0.125*log2(e)
__device__ __half g_k[NTOK*DD];
__device__ __half g_v[NTOK*DD];
__device__ __half g_ctx[NTOK*DD];  // [b][s][h*64+d]
__device__ __half g_x16[NTOK*DD];  // fp16 copy of x
__device__ __half g_wq16[DD*DD];
__device__ __half g_wk16[DD*DD];
__device__ __half g_wv16[DD*DD];
__device__ __half g_wo16[DD*DD];

// ---------------------------------------------------------------------------
// Helpers
// ---------------------------------------------------------------------------
__device__ __forceinline__ uint32_t smem_u32(const void* p) {
    uint32_t a;
    asm("{ .reg .u64 t; cvta.to.shared.u64 t, %1; cvt.u32.u64 %0, t; }"
        : "=r"(a) : "l"(p));
    return a;
}
__device__ __forceinline__ uint32_t f2h2(float lo, float hi) {
    __half2 h = __floats2half2_rn(lo, hi);
    return *reinterpret_cast<uint32_t*>(&h);
}
__device__ __forceinline__ void mma_f16(float d[4], const uint32_t a[4],
                                        const uint32_t* b, const float c[4]) {
    asm volatile(
        "mma.sync.aligned.m16n8k16.row.col.f32.f16.f16.f32 "
        "{%0,%1,%2,%3}, {%4,%5,%6,%7}, {%8,%9}, {%10,%11,%12,%13};"
        : "=f"(d[0]), "=f"(d[1]), "=f"(d[2]), "=f"(d[3])
        : "r"(a[0]), "r"(a[1]), "r"(a[2]), "r"(a[3]),
          "r"(b[0]), "r"(b[1]),
          "f"(c[0]), "f"(c[1]), "f"(c[2]), "f"(c[3]));
}
__device__ __forceinline__ void ldsm_x4(uint32_t r[4], uint32_t addr) {
    asm volatile("ldmatrix.sync.aligned.m8n8.x4.shared.b16 {%0,%1,%2,%3}, [%4];"
        : "=r"(r[0]), "=r"(r[1]), "=r"(r[2]), "=r"(r[3]) : "r"(addr));
}
__device__ __forceinline__ void ldsm_x4_t(uint32_t r[4], uint32_t addr) {
    asm volatile("ldmatrix.sync.aligned.m8n8.x4.trans.shared.b16 {%0,%1,%2,%3}, [%4];"
        : "=r"(r[0]), "=r"(r[1]), "=r"(r[2]), "=r"(r[3]) : "r"(addr));
}
__device__ __forceinline__ void cp_async16(uint32_t saddr, const void* gaddr) {
    asm volatile("cp.async.cg.shared.global [%0], [%1], 16;"
        :: "r"(saddr), "l"(gaddr) : "memory");
}

// ---------------------------------------------------------------------------
// Kernel 0a/0b: fp32 -> fp16 converts
// ---------------------------------------------------------------------------
__global__ __launch_bounds__(256) void cvt_x_kernel(const float4* __restrict__ src,
                                                    uint2* __restrict__ dst, int n4)
{
    const int i = blockIdx.x * 256 + threadIdx.x;
    if (i < n4) {
        const float4 v = src[i];
        uint2 o;
        o.x = f2h2(v.x, v.y);
        o.y = f2h2(v.z, v.w);
        dst[i] = o;
    }
}

__global__ __launch_bounds__(256) void cvt_w_kernel(
    const float4* __restrict__ w0, const float4* __restrict__ w1,
    const float4* __restrict__ w2, const float4* __restrict__ w3,
    uint2* __restrict__ d0, uint2* __restrict__ d1,
    uint2* __restrict__ d2, uint2* __restrict__ d3)
{
    const int i = blockIdx.x * 256 + threadIdx.x;   // < DD*DD/4
    const float4* s = (blockIdx.y == 0) ? w0 : (blockIdx.y == 1) ? w1
                    : (blockIdx.y == 2) ? w2 : w3;
    uint2* d = (blockIdx.y == 0) ? d0 : (blockIdx.y == 1) ? d1
             : (blockIdx.y == 2) ? d2 : d3;
    const float4 v = s[i];
    uint2 o;
    o.x = f2h2(v.x, v.y);
    o.y = f2h2(v.z, v.w);
    d[i] = o;
}

// ---------------------------------------------------------------------------
// fp16 GEMM core: C(128x256) = A[m0:+128,:] @ B[n0:+256,:]^T, K=1024.
// 256 thr = 8 warps (2x4), warp tile 64x64, BK=32, 4-stage cp.async pipeline.
// Smem/stage 24KB: A 128x32h at +0 (8KB), B 256x32h at +8192 (16KB).
// Swizzle: byte = row*64 + ((ch ^ ((row>>1)&3))*16), ch = k>>3.
// ---------------------------------------------------------------------------
#define GSTG 24576u

__device__ __forceinline__ void gemm16_stage(
    const __half* __restrict__ A, const __half* __restrict__ B,
    int m0, int n0, uint32_t sbase, int s, int k0, int tid)
{
    const uint32_t sb = sbase + (uint32_t)s*GSTG;
    #pragma unroll
    for (int j = 0; j < 2; j++) {
        const int id  = tid + j*256;
        const int row = id >> 2;
        const int ch  = id & 3;
        const uint32_t sw = (uint32_t)(row*64 + ((ch ^ ((row>>1)&3))*16));
        cp_async16(sb + sw, A + (size_t)(m0 + row)*DD + k0 + ch*8);
    }
    #pragma unroll
    for (int j = 0; j < 4; j++) {
        const int id  = tid + j*256;
        const int row = id >> 2;
        const int ch  = id & 3;
        const uint32_t sw = (uint32_t)(row*64 + ((ch ^ ((row>>1)&3))*16));
        cp_async16(sb + 8192u + sw, B + (size_t)(n0 + row)*DD + k0 + ch*8);
    }
    asm volatile("cp.async.commit_group;" ::: "memory");
}

__device__ __forceinline__ void gemm16_core(
    const __half* __restrict__ A, const __half* __restrict__ B,
    int m0, int n0, uint32_t sbase, float acc[4][8][4])
{
    const int tid  = threadIdx.x;
    const int lane = tid & 31;
    const int warp = tid >> 5;
    const int wm = warp >> 2;        // 0..1 (64 m-rows)
    const int wn = warp & 3;         // 0..3 (64 n-cols)

    const int a_row_off = (lane & 7) + ((lane >> 3) & 1) * 8;
    const int a_ch_off  = lane >> 4;
    const int b_row_off = ((lane >> 4) << 3) + (lane & 7);
    const int b_ch_off  = (lane >> 3) & 1;

    gemm16_stage(A, B, m0, n0, sbase, 0, 0,  tid);
    gemm16_stage(A, B, m0, n0, sbase, 1, 32, tid);
    gemm16_stage(A, B, m0, n0, sbase, 2, 64, tid);

    for (int i = 0; i < 32; i++) {
        if (i < 30)       { asm volatile("cp.async.wait_group 2;" ::: "memory"); }
        else if (i == 30) { asm volatile("cp.async.wait_group 1;" ::: "memory"); }
        else              { asm volatile("cp.async.wait_group 0;" ::: "memory"); }
        __syncthreads();

        if (i + 3 < 32)
            gemm16_stage(A, B, m0, n0, sbase, (i+3) & 3, (i+3)*32, tid);

        const uint32_t sA = sbase + (uint32_t)(i & 3)*GSTG;
        const uint32_t sB = sA + 8192u;

        #pragma unroll
        for (int ks = 0; ks < 2; ks++) {
            uint32_t af[4][4];
            #pragma unroll
            for (int mt = 0; mt < 4; mt++) {
                const int row = wm*64 + mt*16 + a_row_off;
                const int ch  = 2*ks + a_ch_off;
                ldsm_x4(af[mt], sA + (uint32_t)(row*64 + ((ch ^ ((row>>1)&3))*16)));
            }
            uint32_t bf[8][2];
            #pragma unroll
            for (int pr = 0; pr < 4; pr++) {
                const int row = wn*64 + pr*16 + b_row_off;
                const int ch  = 2*ks + b_ch_off;
                uint32_t t[4];
                ldsm_x4(t, sB + (uint32_t)(row*64 + ((ch ^ ((row>>1)&3))*16)));
                bf[pr*2  ][0] = t[0]; bf[pr*2  ][1] = t[1];
                bf[pr*2+1][0] = t[2]; bf[pr*2+1][1] = t[3];
            }
            #pragma unroll
            for (int mt = 0; mt < 4; mt++)
                #pragma unroll
                for (int nt = 0; nt < 8; nt++)
                    mma_f16(acc[mt][nt], af[mt], bf[nt], acc[mt][nt]);
        }
    }
}

// ---------------------------------------------------------------------------
// Kernel 1: fused QKV projection. grid (4, 32, 3), block 256. fp16 in/out.
// ---------------------------------------------------------------------------
#define QSCALE 0.1803368801111743f   // 0.125 * log2(e)

__global__ __launch_bounds__(256) void qkv_gemm_kernel()
{
    extern __shared__ char smg[];
    const uint32_t sbase = smem_u32(smg);

    const __half* W   = (blockIdx.z == 0) ? g_wq16 : (blockIdx.z == 1) ? g_wk16 : g_wv16;
    __half*       out = (blockIdx.z == 0) ? g_q    : (blockIdx.z == 1) ? g_k    : g_v;
    const float oscale = (blockIdx.z == 0) ? QSCALE : 1.0f;

    const int m0 = blockIdx.y * 128;
    const int n0 = blockIdx.x * 256;

    float acc[4][8][4];
    #pragma unroll
    for (int i = 0; i < 4; i++)
        #pragma unroll
        for (int j = 0; j < 8; j++)
            #pragma unroll
            for (int k = 0; k < 4; k++) acc[i][j][k] = 0.f;

    gemm16_core(g_x16, W, m0, n0, sbase, acc);

    const int lane = threadIdx.x & 31;
    const int warp = threadIdx.x >> 5;
    const int wm = warp >> 2, wn = warp & 3;
    const int r = lane >> 2, c = lane & 3;

    #pragma unroll
    for (int mt = 0; mt < 4; mt++) {
        #pragma unroll
        for (int nt = 0; nt < 8; nt++) {
            #pragma unroll
            for (int half = 0; half < 2; half++) {
                const int m = m0 + wm*64 + mt*16 + r + half*8;
                const int b = m >> 11;
                const int s = m & 2047;
                const int n = n0 + wn*64 + nt*8 + c*2;
                const int h = n >> 6;
                const int d = n & 63;
                const uint32_t v = f2h2(acc[mt][nt][half*2+0]*oscale,
                                        acc[mt][nt][half*2+1]*oscale);
                *reinterpret_cast<uint32_t*>(
                    out + (((size_t)(b*NH + h))*SS + s)*HDIM + d) = v;
            }
        }
    }
}

// ---------------------------------------------------------------------------
// Kernel 3: output projection + bias. grid (4, 32), block 256.
// ---------------------------------------------------------------------------
__global__ __launch_bounds__(256) void oproj_kernel(
    const float* __restrict__ bo,
    float* __restrict__ out)
{
    extern __shared__ char smg[];
    const uint32_t sbase = smem_u32(smg);

    const int m0 = blockIdx.y * 128;
    const int n0 = blockIdx.x * 256;

    float acc[4][8][4];
    #pragma unroll
    for (int i = 0; i < 4; i++)
        #pragma unroll
        for (int j = 0; j < 8; j++)
            #pragma unroll
            for (int k = 0; k < 4; k++) acc[i][j][k] = 0.f;

    gemm16_core(g_ctx, g_wo16, m0, n0, sbase, acc);

    const int lane = threadIdx.x & 31;
    const int warp = threadIdx.x >> 5;
    const int wm = warp >> 2, wn = warp & 3;
    const int r = lane >> 2, c = lane & 3;

    #pragma unroll
    for (int mt = 0; mt < 4; mt++) {
        #pragma unroll
        for (int nt = 0; nt < 8; nt++) {
            #pragma unroll
            for (int half = 0; half < 2; half++) {
                const int m = m0 + wm*64 + mt*16 + r + half*8;
                const int n = n0 + wn*64 + nt*8 + c*2;
                float* o = out + (size_t)m*DD + n;
                o[0] = acc[mt][nt][half*2 + 0] + bo[n];
                o[1] = acc[mt][nt][half*2 + 1] + bo[n + 1];
            }
        }
    }
}

// ---------------------------------------------------------------------------
// Kernel 2: causal flash attention (log2 softmax, l via P@ones mma,
// warp-uniform rescale skip). grid (16, 32), block 256, KV tile 64.
// ---------------------------------------------------------------------------
#define ASTG 16384u

__global__ __launch_bounds__(256) void attn_kernel()
{
    __shared__ __align__(16) char smA[2*ASTG];
    const uint32_t sbase = smem_u32(smA);

    const int tid  = threadIdx.x;
    const int lane = tid & 31;
    const int warp = tid >> 5;
    const int r = lane >> 2;
    const int c = lane & 3;
    const int qt = 15 - blockIdx.x;      // heavy CTAs first
    const int bh = blockIdx.y;

    const __half* Qg = g_q + (size_t)bh * SS * HDIM;
    const __half* Kg = g_k + (size_t)bh * SS * HDIM;
    const __half* Vg = g_v + (size_t)bh * SS * HDIM;
    const uint32_t* Qg2 = reinterpret_cast<const uint32_t*>(Qg);
    const int q0 = qt * 128;
    const int qbase = q0 + warp * 16;

    // Q fragments (g_q pre-scaled by 0.125*log2e)
    uint32_t qf[4][4];
    #pragma unroll
    for (int kk = 0; kk < 4; kk++) {
        qf[kk][0] = Qg2[(size_t)(qbase + r    )*32 + kk*8 + c    ];
        qf[kk][1] = Qg2[(size_t)(qbase + r + 8)*32 + kk*8 + c    ];
        qf[kk][2] = Qg2[(size_t)(qbase + r    )*32 + kk*8 + c + 4];
        qf[kk][3] = Qg2[(size_t)(qbase + r + 8)*32 + kk*8 + c + 4];
    }

    const int k_key_off = ((lane >> 4) & 1) * 8 + (lane & 7);
    const int k_ch_off  = (lane >> 3) & 1;
    const int v_key_off = ((lane >> 3) & 1) * 8 + (lane & 7);
    const int v_ch_off  = (lane >> 4);

    const uint32_t ones2[2] = { 0x3C003C00u, 0x3C003C00u };  // fp16 1.0 x2

    float of[8][4];
    #pragma unroll
    for (int nt = 0; nt < 8; nt++)
        #pragma unroll
        for (int j = 0; j < 4; j++) of[nt][j] = 0.f;
    float lc[4] = {0.f, 0.f, 0.f, 0.f};   // row-sum accumulator (P @ ones)
    float m0i = -1e30f, m1i = -1e30f;

    auto stage = [&](int kt, int s) {
        const uint32_t sb = sbase + (uint32_t)s * ASTG;
        #pragma unroll
        for (int j = 0; j < 2; j++) {
            const int id  = tid + j*256;
            const int row = id >> 3;
            const int ch  = id & 7;
            const uint32_t sw = (uint32_t)(row*128 + ((ch ^ (row & 7))*16));
            cp_async16(sb + sw,          Kg + (size_t)(kt*64 + row)*HDIM + ch*8);
            cp_async16(sb + 8192u + sw,  Vg + (size_t)(kt*64 + row)*HDIM + ch*8);
        }
        asm volatile("cp.async.commit_group;" ::: "memory");
    };

    const int ktmax = 2*qt + 1;
    stage(0, 0);

    for (int kt = 0; kt <= ktmax; kt++) {
        asm volatile("cp.async.wait_group 0;" ::: "memory");
        __syncthreads();
        if (kt < ktmax) stage(kt + 1, (kt + 1) & 1);

        if (kt*64 > qbase + 15) continue;

        const uint32_t sK = sbase + (uint32_t)(kt & 1) * ASTG;
        const uint32_t sV = sK + 8192u;

        // ---- S = Q @ K^T (log2 domain) ----
        float sf[8][4];
        #pragma unroll
        for (int nt = 0; nt < 8; nt++)
            #pragma unroll
            for (int j = 0; j < 4; j++) sf[nt][j] = 0.f;

        #pragma unroll
        for (int kk = 0; kk < 4; kk++) {
            #pragma unroll
            for (int ntp = 0; ntp < 4; ntp++) {
                const int key = ntp*16 + k_key_off;
                const int ch  = 2*kk + k_ch_off;
                uint32_t t[4];
                ldsm_x4(t, sK + (uint32_t)(key*128 + ((ch ^ (key & 7))*16)));
                mma_f16(sf[2*ntp    ], qf[kk], &t[0], sf[2*ntp    ]);
                mma_f16(sf[2*ntp + 1], qf[kk], &t[2], sf[2*ntp + 1]);
            }
        }

        // ---- causal mask (boundary tiles only) ----
        const int qg0 = qbase + r;
        const int qg1 = qg0 + 8;
        if (kt*64 + 63 > qbase) {
            #pragma unroll
            for (int nt = 0; nt < 8; nt++) {
                const int col0 = kt*64 + nt*8 + c*2;
                if (col0     > qg0) sf[nt][0] = -1e30f;
                if (col0 + 1 > qg0) sf[nt][1] = -1e30f;
                if (col0     > qg1) sf[nt][2] = -1e30f;
                if (col0 + 1 > qg1) sf[nt][3] = -1e30f;
            }
        }

        // ---- online softmax (base-2) ----
        float mx0 = -1e30f, mx1 = -1e30f;
        #pragma unroll
        for (int nt = 0; nt < 8; nt++) {
            mx0 = fmaxf(mx0, fmaxf(sf[nt][0], sf[nt][1]));
            mx1 = fmaxf(mx1, fmaxf(sf[nt][2], sf[nt][3]));
        }
        mx0 = fmaxf(mx0, __shfl_xor_sync(0xffffffffu, mx0, 1));
        mx0 = fmaxf(mx0, __shfl_xor_sync(0xffffffffu, mx0, 2));
        mx1 = fmaxf(mx1, __shfl_xor_sync(0xffffffffu, mx1, 1));
        mx1 = fmaxf(mx1, __shfl_xor_sync(0xffffffffu, mx1, 2));

        const float mn0 = fmaxf(m0i, mx0);
        const float mn1 = fmaxf(m1i, mx1);

        // exp + pack P into A-fragments
        uint32_t pk[4][4];
        #pragma unroll
        for (int nt = 0; nt < 8; nt++) {
            const float p00 = exp2f(sf[nt][0] - mn0);
            const float p01 = exp2f(sf[nt][1] - mn0);
            const float p10 = exp2f(sf[nt][2] - mn1);
            const float p11 = exp2f(sf[nt][3] - mn1);
            pk[nt >> 1][(nt & 1)*2    ] = f2h2(p00, p01);
            pk[nt >> 1][(nt & 1)*2 + 1] = f2h2(p10, p11);
        }

        // rescale accumulators only when any row's max moved (exact skip: cor==1)
        const bool chg = (mn0 > m0i) || (mn1 > m1i);
        if (__any_sync(0xffffffffu, chg)) {
            const float cor0 = exp2f(m0i - mn0);
            const float cor1 = exp2f(m1i - mn1);
            lc[0] *= cor0; lc[1] *= cor0; lc[2] *= cor1; lc[3] *= cor1;
            #pragma unroll
            for (int nt = 0; nt < 8; nt++) {
                of[nt][0] *= cor0;
                of[nt][1] *= cor0;
                of[nt][2] *= cor1;
                of[nt][3] *= cor1;
            }
        }
        m0i = mn0;
        m1i = mn1;

        // l += P @ ones (tensor pipe; every lane ends with the row sums)
        #pragma unroll
        for (int kk = 0; kk < 4; kk++)
            mma_f16(lc, pk[kk], ones2, lc);

        // ---- O += P @ V ----
        #pragma unroll
        for (int kk = 0; kk < 4; kk++) {
            #pragma unroll
            for (int ntp = 0; ntp < 4; ntp++) {
                const int key = 16*kk + v_key_off;
                const int ch  = 2*ntp + v_ch_off;
                uint32_t t[4];
                ldsm_x4_t(t, sV + (uint32_t)(key*128 + ((ch ^ (key & 7))*16)));
                mma_f16(of[2*ntp    ], pk[kk], &t[0], of[2*ntp    ]);
                mma_f16(of[2*ntp + 1], pk[kk], &t[2], of[2*ntp + 1]);
            }
        }
    }

    // epilogue: normalize, write ctx (fp16) [b][s][h*64+d]
    const int b = bh >> 4, h = bh & 15;
    const float inv0 = 1.0f / lc[0];
    const float inv1 = 1.0f / lc[2];
    const int qg0 = qbase + r;
    #pragma unroll
    for (int nt = 0; nt < 8; nt++) {
        const int d = nt*8 + c*2;
        *reinterpret_cast<uint32_t*>(
            g_ctx + ((size_t)(b*SS + qg0    ))*DD + h*HDIM + d) = f2h2(of[nt][0]*inv0, of[nt][1]*inv0);
        *reinterpret_cast<uint32_t*>(
            g_ctx + ((size_t)(b*SS + qg0 + 8))*DD + h*HDIM + d) = f2h2(of[nt][2]*inv1, of[nt][3]*inv1);
    }
}

// ---------------------------------------------------------------------------
// Launch
// ---------------------------------------------------------------------------
extern "C" void kernel_launch(void* const* d_in, const int* in_sizes, int n_in,
                              void* d_out, int out_size)
{
    const float* x  = (const float*)d_in[0];
    const float* Wq = (const float*)d_in[1];
    const float* Wk = (const float*)d_in[2];
    const float* Wv = (const float*)d_in[3];
    const float* Wo = (const float*)d_in[4];
    const float* bo = (const float*)d_in[5];
    float* out = (float*)d_out;

    (void)in_sizes; (void)n_in; (void)out_size;

    __half* dx;  cudaGetSymbolAddress((void**)&dx,  g_x16);
    __half* dwq; cudaGetSymbolAddress((void**)&dwq, g_wq16);
    __half* dwk; cudaGetSymbolAddress((void**)&dwk, g_wk16);
    __half* dwv; cudaGetSymbolAddress((void**)&dwv, g_wv16);
    __half* dwo; cudaGetSymbolAddress((void**)&dwo, g_wo16);

    const int nx4 = NTOK*DD/4;   // 1M
    const int nw4 = DD*DD/4;     // 256K
    cvt_x_kernel<<<nx4/256, 256>>>((const float4*)x, (uint2*)dx, nx4);
    cvt_w_kernel<<<dim3(nw4/256, 4), 256>>>(
        (const float4*)Wq, (const float4*)Wk, (const float4*)Wv, (const float4*)Wo,
        (uint2*)dwq, (uint2*)dwk, (uint2*)dwv, (uint2*)dwo);

    const int gsm = 4 * GSTG;   // 98304 bytes dynamic smem (4-stage pipeline)
    cudaFuncSetAttribute(qkv_gemm_kernel,
                         cudaFuncAttributeMaxDynamicSharedMemorySize, gsm);
    cudaFuncSetAttribute(oproj_kernel,
                         cudaFuncAttributeMaxDynamicSharedMemorySize, gsm);

    qkv_gemm_kernel<<<dim3(4, 32, 3), 256, gsm>>>();
    attn_kernel<<<dim3(16, 32), 256>>>();
    oproj_kernel<<<dim3(4, 32), 256, gsm>>>(bo, out);
}

// round 10
// speedup vs baseline: 6.7823x; 1.0074x over previous
#include <cuda_runtime.h>
#include <cuda_fp16.h>
#include <math.h>
#include <stdint.h>

#define BB   2
#define SS   2048
#define DD   1024
#define NH   16
#define HDIM 64
#define NTOK (BB*SS)

// Scratch (device globals: allocation-free per harness rules)
__device__ __half g_q[NTOK*DD];    // [b][h][s][d], pre-scaled by 0.125*log2(e)
__device__ __half g_k[NTOK*DD];
__device__ __half g_v[NTOK*DD];
__device__ __half g_ctx[NTOK*DD];  // [b][s][h*64+d]
__device__ __half g_x16[NTOK*DD];  // fp16 copy of x
__device__ __half g_wq16[DD*DD];
__device__ __half g_wk16[DD*DD];
__device__ __half g_wv16[DD*DD];
__device__ __half g_wo16[DD*DD];

// ---------------------------------------------------------------------------
// Helpers
// ---------------------------------------------------------------------------
__device__ __forceinline__ uint32_t smem_u32(const void* p) {
    uint32_t a;
    asm("{ .reg .u64 t; cvta.to.shared.u64 t, %1; cvt.u32.u64 %0, t; }"
        : "=r"(a) : "l"(p));
    return a;
}
__device__ __forceinline__ uint32_t f2h2(float lo, float hi) {
    __half2 h = __floats2half2_rn(lo, hi);
    return *reinterpret_cast<uint32_t*>(&h);
}
__device__ __forceinline__ uint32_t hsub2(uint32_t a, uint32_t b) {
    uint32_t d;
    asm("sub.f16x2 %0, %1, %2;" : "=r"(d) : "r"(a), "r"(b));
    return d;
}
__device__ __forceinline__ uint32_t ex2h2(uint32_t a) {
    uint32_t d;
    asm("ex2.approx.f16x2 %0, %1;" : "=r"(d) : "r"(a));
    return d;
}
__device__ __forceinline__ void mma_f16(float d[4], const uint32_t a[4],
                                        const uint32_t* b, const float c[4]) {
    asm volatile(
        "mma.sync.aligned.m16n8k16.row.col.f32.f16.f16.f32 "
        "{%0,%1,%2,%3}, {%4,%5,%6,%7}, {%8,%9}, {%10,%11,%12,%13};"
        : "=f"(d[0]), "=f"(d[1]), "=f"(d[2]), "=f"(d[3])
        : "r"(a[0]), "r"(a[1]), "r"(a[2]), "r"(a[3]),
          "r"(b[0]), "r"(b[1]),
          "f"(c[0]), "f"(c[1]), "f"(c[2]), "f"(c[3]));
}
__device__ __forceinline__ void ldsm_x4(uint32_t r[4], uint32_t addr) {
    asm volatile("ldmatrix.sync.aligned.m8n8.x4.shared.b16 {%0,%1,%2,%3}, [%4];"
        : "=r"(r[0]), "=r"(r[1]), "=r"(r[2]), "=r"(r[3]) : "r"(addr));
}
__device__ __forceinline__ void ldsm_x4_t(uint32_t r[4], uint32_t addr) {
    asm volatile("ldmatrix.sync.aligned.m8n8.x4.trans.shared.b16 {%0,%1,%2,%3}, [%4];"
        : "=r"(r[0]), "=r"(r[1]), "=r"(r[2]), "=r"(r[3]) : "r"(addr));
}
__device__ __forceinline__ void cp_async16(uint32_t saddr, const void* gaddr) {
    asm volatile("cp.async.cg.shared.global [%0], [%1], 16;"
        :: "r"(saddr), "l"(gaddr) : "memory");
}

// ---------------------------------------------------------------------------
// Kernel 0a/0b: fp32 -> fp16 converts
// ---------------------------------------------------------------------------
__global__ __launch_bounds__(256) void cvt_x_kernel(const float4* __restrict__ src,
                                                    uint2* __restrict__ dst, int n4)
{
    const int i = blockIdx.x * 256 + threadIdx.x;
    if (i < n4) {
        const float4 v = src[i];
        uint2 o;
        o.x = f2h2(v.x, v.y);
        o.y = f2h2(v.z, v.w);
        dst[i] = o;
    }
}

__global__ __launch_bounds__(256) void cvt_w_kernel(
    const float4* __restrict__ w0, const float4* __restrict__ w1,
    const float4* __restrict__ w2, const float4* __restrict__ w3,
    uint2* __restrict__ d0, uint2* __restrict__ d1,
    uint2* __restrict__ d2, uint2* __restrict__ d3)
{
    const int i = blockIdx.x * 256 + threadIdx.x;   // < DD*DD/4
    const float4* s = (blockIdx.y == 0) ? w0 : (blockIdx.y == 1) ? w1
                    : (blockIdx.y == 2) ? w2 : w3;
    uint2* d = (blockIdx.y == 0) ? d0 : (blockIdx.y == 1) ? d1
             : (blockIdx.y == 2) ? d2 : d3;
    const float4 v = s[i];
    uint2 o;
    o.x = f2h2(v.x, v.y);
    o.y = f2h2(v.z, v.w);
    d[i] = o;
}

// ---------------------------------------------------------------------------
// fp16 GEMM core (unchanged from round 9): C(128x256), 4-stage cp.async.
// ---------------------------------------------------------------------------
#define GSTG 24576u

__device__ __forceinline__ void gemm16_stage(
    const __half* __restrict__ A, const __half* __restrict__ B,
    int m0, int n0, uint32_t sbase, int s, int k0, int tid)
{
    const uint32_t sb = sbase + (uint32_t)s*GSTG;
    #pragma unroll
    for (int j = 0; j < 2; j++) {
        const int id  = tid + j*256;
        const int row = id >> 2;
        const int ch  = id & 3;
        const uint32_t sw = (uint32_t)(row*64 + ((ch ^ ((row>>1)&3))*16));
        cp_async16(sb + sw, A + (size_t)(m0 + row)*DD + k0 + ch*8);
    }
    #pragma unroll
    for (int j = 0; j < 4; j++) {
        const int id  = tid + j*256;
        const int row = id >> 2;
        const int ch  = id & 3;
        const uint32_t sw = (uint32_t)(row*64 + ((ch ^ ((row>>1)&3))*16));
        cp_async16(sb + 8192u + sw, B + (size_t)(n0 + row)*DD + k0 + ch*8);
    }
    asm volatile("cp.async.commit_group;" ::: "memory");
}

__device__ __forceinline__ void gemm16_core(
    const __half* __restrict__ A, const __half* __restrict__ B,
    int m0, int n0, uint32_t sbase, float acc[4][8][4])
{
    const int tid  = threadIdx.x;
    const int lane = tid & 31;
    const int warp = tid >> 5;
    const int wm = warp >> 2;        // 0..1 (64 m-rows)
    const int wn = warp & 3;         // 0..3 (64 n-cols)

    const int a_row_off = (lane & 7) + ((lane >> 3) & 1) * 8;
    const int a_ch_off  = lane >> 4;
    const int b_row_off = ((lane >> 4) << 3) + (lane & 7);
    const int b_ch_off  = (lane >> 3) & 1;

    gemm16_stage(A, B, m0, n0, sbase, 0, 0,  tid);
    gemm16_stage(A, B, m0, n0, sbase, 1, 32, tid);
    gemm16_stage(A, B, m0, n0, sbase, 2, 64, tid);

    for (int i = 0; i < 32; i++) {
        if (i < 30)       { asm volatile("cp.async.wait_group 2;" ::: "memory"); }
        else if (i == 30) { asm volatile("cp.async.wait_group 1;" ::: "memory"); }
        else              { asm volatile("cp.async.wait_group 0;" ::: "memory"); }
        __syncthreads();

        if (i + 3 < 32)
            gemm16_stage(A, B, m0, n0, sbase, (i+3) & 3, (i+3)*32, tid);

        const uint32_t sA = sbase + (uint32_t)(i & 3)*GSTG;
        const uint32_t sB = sA + 8192u;

        #pragma unroll
        for (int ks = 0; ks < 2; ks++) {
            uint32_t af[4][4];
            #pragma unroll
            for (int mt = 0; mt < 4; mt++) {
                const int row = wm*64 + mt*16 + a_row_off;
                const int ch  = 2*ks + a_ch_off;
                ldsm_x4(af[mt], sA + (uint32_t)(row*64 + ((ch ^ ((row>>1)&3))*16)));
            }
            uint32_t bf[8][2];
            #pragma unroll
            for (int pr = 0; pr < 4; pr++) {
                const int row = wn*64 + pr*16 + b_row_off;
                const int ch  = 2*ks + b_ch_off;
                uint32_t t[4];
                ldsm_x4(t, sB + (uint32_t)(row*64 + ((ch ^ ((row>>1)&3))*16)));
                bf[pr*2  ][0] = t[0]; bf[pr*2  ][1] = t[1];
                bf[pr*2+1][0] = t[2]; bf[pr*2+1][1] = t[3];
            }
            #pragma unroll
            for (int mt = 0; mt < 4; mt++)
                #pragma unroll
                for (int nt = 0; nt < 8; nt++)
                    mma_f16(acc[mt][nt], af[mt], bf[nt], acc[mt][nt]);
        }
    }
}

// ---------------------------------------------------------------------------
// Kernel 1: fused QKV projection. grid (4, 32, 3), block 256. fp16 in/out.
// ---------------------------------------------------------------------------
#define QSCALE 0.1803368801111743f   // 0.125 * log2(e)

__global__ __launch_bounds__(256) void qkv_gemm_kernel()
{
    extern __shared__ char smg[];
    const uint32_t sbase = smem_u32(smg);

    const __half* W   = (blockIdx.z == 0) ? g_wq16 : (blockIdx.z == 1) ? g_wk16 : g_wv16;
    __half*       out = (blockIdx.z == 0) ? g_q    : (blockIdx.z == 1) ? g_k    : g_v;
    const float oscale = (blockIdx.z == 0) ? QSCALE : 1.0f;

    const int m0 = blockIdx.y * 128;
    const int n0 = blockIdx.x * 256;

    float acc[4][8][4];
    #pragma unroll
    for (int i = 0; i < 4; i++)
        #pragma unroll
        for (int j = 0; j < 8; j++)
            #pragma unroll
            for (int k = 0; k < 4; k++) acc[i][j][k] = 0.f;

    gemm16_core(g_x16, W, m0, n0, sbase, acc);

    const int lane = threadIdx.x & 31;
    const int warp = threadIdx.x >> 5;
    const int wm = warp >> 2, wn = warp & 3;
    const int r = lane >> 2, c = lane & 3;

    #pragma unroll
    for (int mt = 0; mt < 4; mt++) {
        #pragma unroll
        for (int nt = 0; nt < 8; nt++) {
            #pragma unroll
            for (int half = 0; half < 2; half++) {
                const int m = m0 + wm*64 + mt*16 + r + half*8;
                const int b = m >> 11;
                const int s = m & 2047;
                const int n = n0 + wn*64 + nt*8 + c*2;
                const int h = n >> 6;
                const int d = n & 63;
                const uint32_t v = f2h2(acc[mt][nt][half*2+0]*oscale,
                                        acc[mt][nt][half*2+1]*oscale);
                *reinterpret_cast<uint32_t*>(
                    out + (((size_t)(b*NH + h))*SS + s)*HDIM + d) = v;
            }
        }
    }
}

// ---------------------------------------------------------------------------
// Kernel 3: output projection + bias. grid (4, 32), block 256.
// ---------------------------------------------------------------------------
__global__ __launch_bounds__(256) void oproj_kernel(
    const float* __restrict__ bo,
    float* __restrict__ out)
{
    extern __shared__ char smg[];
    const uint32_t sbase = smem_u32(smg);

    const int m0 = blockIdx.y * 128;
    const int n0 = blockIdx.x * 256;

    float acc[4][8][4];
    #pragma unroll
    for (int i = 0; i < 4; i++)
        #pragma unroll
        for (int j = 0; j < 8; j++)
            #pragma unroll
            for (int k = 0; k < 4; k++) acc[i][j][k] = 0.f;

    gemm16_core(g_ctx, g_wo16, m0, n0, sbase, acc);

    const int lane = threadIdx.x & 31;
    const int warp = threadIdx.x >> 5;
    const int wm = warp >> 2, wn = warp & 3;
    const int r = lane >> 2, c = lane & 3;

    #pragma unroll
    for (int mt = 0; mt < 4; mt++) {
        #pragma unroll
        for (int nt = 0; nt < 8; nt++) {
            #pragma unroll
            for (int half = 0; half < 2; half++) {
                const int m = m0 + wm*64 + mt*16 + r + half*8;
                const int n = n0 + wn*64 + nt*8 + c*2;
                float* o = out + (size_t)m*DD + n;
                o[0] = acc[mt][nt][half*2 + 0] + bo[n];
                o[1] = acc[mt][nt][half*2 + 1] + bo[n + 1];
            }
        }
    }
}

// ---------------------------------------------------------------------------
// Kernel 2: causal flash attention. log2 softmax with packed fp16 exp
// (ex2.approx.f16x2), l via P@ones mma, rescale skip. grid (16, 32).
// ---------------------------------------------------------------------------
#define ASTG 16384u

__global__ __launch_bounds__(256) void attn_kernel()
{
    __shared__ __align__(16) char smA[2*ASTG];
    const uint32_t sbase = smem_u32(smA);

    const int tid  = threadIdx.x;
    const int lane = tid & 31;
    const int warp = tid >> 5;
    const int r = lane >> 2;
    const int c = lane & 3;
    const int qt = 15 - blockIdx.x;      // heavy CTAs first
    const int bh = blockIdx.y;

    const __half* Qg = g_q + (size_t)bh * SS * HDIM;
    const __half* Kg = g_k + (size_t)bh * SS * HDIM;
    const __half* Vg = g_v + (size_t)bh * SS * HDIM;
    const uint32_t* Qg2 = reinterpret_cast<const uint32_t*>(Qg);
    const int q0 = qt * 128;
    const int qbase = q0 + warp * 16;

    // Q fragments (g_q pre-scaled by 0.125*log2e)
    uint32_t qf[4][4];
    #pragma unroll
    for (int kk = 0; kk < 4; kk++) {
        qf[kk][0] = Qg2[(size_t)(qbase + r    )*32 + kk*8 + c    ];
        qf[kk][1] = Qg2[(size_t)(qbase + r + 8)*32 + kk*8 + c    ];
        qf[kk][2] = Qg2[(size_t)(qbase + r    )*32 + kk*8 + c + 4];
        qf[kk][3] = Qg2[(size_t)(qbase + r + 8)*32 + kk*8 + c + 4];
    }

    const int k_key_off = ((lane >> 4) & 1) * 8 + (lane & 7);
    const int k_ch_off  = (lane >> 3) & 1;
    const int v_key_off = ((lane >> 3) & 1) * 8 + (lane & 7);
    const int v_ch_off  = (lane >> 4);

    const uint32_t ones2[2] = { 0x3C003C00u, 0x3C003C00u };  // fp16 1.0 x2

    float of[8][4];
    #pragma unroll
    for (int nt = 0; nt < 8; nt++)
        #pragma unroll
        for (int j = 0; j < 4; j++) of[nt][j] = 0.f;
    float lc[4] = {0.f, 0.f, 0.f, 0.f};   // row-sum accumulator (P @ ones)
    float m0i = -1e30f, m1i = -1e30f;

    auto stage = [&](int kt, int s) {
        const uint32_t sb = sbase + (uint32_t)s * ASTG;
        #pragma unroll
        for (int j = 0; j < 2; j++) {
            const int id  = tid + j*256;
            const int row = id >> 3;
            const int ch  = id & 7;
            const uint32_t sw = (uint32_t)(row*128 + ((ch ^ (row & 7))*16));
            cp_async16(sb + sw,          Kg + (size_t)(kt*64 + row)*HDIM + ch*8);
            cp_async16(sb + 8192u + sw,  Vg + (size_t)(kt*64 + row)*HDIM + ch*8);
        }
        asm volatile("cp.async.commit_group;" ::: "memory");
    };

    const int ktmax = 2*qt + 1;
    stage(0, 0);

    for (int kt = 0; kt <= ktmax; kt++) {
        asm volatile("cp.async.wait_group 0;" ::: "memory");
        __syncthreads();
        if (kt < ktmax) stage(kt + 1, (kt + 1) & 1);

        if (kt*64 > qbase + 15) continue;

        const uint32_t sK = sbase + (uint32_t)(kt & 1) * ASTG;
        const uint32_t sV = sK + 8192u;

        // ---- S = Q @ K^T (log2 domain) ----
        float sf[8][4];
        #pragma unroll
        for (int nt = 0; nt < 8; nt++)
            #pragma unroll
            for (int j = 0; j < 4; j++) sf[nt][j] = 0.f;

        #pragma unroll
        for (int kk = 0; kk < 4; kk++) {
            #pragma unroll
            for (int ntp = 0; ntp < 4; ntp++) {
                const int key = ntp*16 + k_key_off;
                const int ch  = 2*kk + k_ch_off;
                uint32_t t[4];
                ldsm_x4(t, sK + (uint32_t)(key*128 + ((ch ^ (key & 7))*16)));
                mma_f16(sf[2*ntp    ], qf[kk], &t[0], sf[2*ntp    ]);
                mma_f16(sf[2*ntp + 1], qf[kk], &t[2], sf[2*ntp + 1]);
            }
        }

        // ---- causal mask (boundary tiles only) ----
        const int qg0 = qbase + r;
        const int qg1 = qg0 + 8;
        if (kt*64 + 63 > qbase) {
            #pragma unroll
            for (int nt = 0; nt < 8; nt++) {
                const int col0 = kt*64 + nt*8 + c*2;
                if (col0     > qg0) sf[nt][0] = -1e30f;
                if (col0 + 1 > qg0) sf[nt][1] = -1e30f;
                if (col0     > qg1) sf[nt][2] = -1e30f;
                if (col0 + 1 > qg1) sf[nt][3] = -1e30f;
            }
        }

        // ---- online softmax (base-2, packed fp16 exp) ----
        float mx0 = -1e30f, mx1 = -1e30f;
        #pragma unroll
        for (int nt = 0; nt < 8; nt++) {
            mx0 = fmaxf(mx0, fmaxf(sf[nt][0], sf[nt][1]));
            mx1 = fmaxf(mx1, fmaxf(sf[nt][2], sf[nt][3]));
        }
        mx0 = fmaxf(mx0, __shfl_xor_sync(0xffffffffu, mx0, 1));
        mx0 = fmaxf(mx0, __shfl_xor_sync(0xffffffffu, mx0, 2));
        mx1 = fmaxf(mx1, __shfl_xor_sync(0xffffffffu, mx1, 1));
        mx1 = fmaxf(mx1, __shfl_xor_sync(0xffffffffu, mx1, 2));

        const float mn0 = fmaxf(m0i, mx0);
        const float mn1 = fmaxf(m1i, mx1);

        // packed exp: cvt pair -> HSUB2 broadcast max -> ex2.approx.f16x2
        const uint32_t mn0h2 = f2h2(mn0, mn0);
        const uint32_t mn1h2 = f2h2(mn1, mn1);
        uint32_t pk[4][4];
        #pragma unroll
        for (int nt = 0; nt < 8; nt++) {
            const uint32_t a = f2h2(sf[nt][0], sf[nt][1]);   // row0 pair
            const uint32_t b = f2h2(sf[nt][2], sf[nt][3]);   // row1 pair
            pk[nt >> 1][(nt & 1)*2    ] = ex2h2(hsub2(a, mn0h2));
            pk[nt >> 1][(nt & 1)*2 + 1] = ex2h2(hsub2(b, mn1h2));
        }

        // rescale accumulators only when a max moved (exact skip: cor==1)
        const bool chg = (mn0 > m0i) || (mn1 > m1i);
        if (__any_sync(0xffffffffu, chg)) {
            const float cor0 = exp2f(m0i - mn0);
            const float cor1 = exp2f(m1i - mn1);
            lc[0] *= cor0; lc[1] *= cor0; lc[2] *= cor1; lc[3] *= cor1;
            #pragma unroll
            for (int nt = 0; nt < 8; nt++) {
                of[nt][0] *= cor0;
                of[nt][1] *= cor0;
                of[nt][2] *= cor1;
                of[nt][3] *= cor1;
            }
        }
        m0i = mn0;
        m1i = mn1;

        // l += P @ ones (tensor pipe; lanes get their rows' sums in lc[0]/lc[2])
        #pragma unroll
        for (int kk = 0; kk < 4; kk++)
            mma_f16(lc, pk[kk], ones2, lc);

        // ---- O += P @ V ----
        #pragma unroll
        for (int kk = 0; kk < 4; kk++) {
            #pragma unroll
            for (int ntp = 0; ntp < 4; ntp++) {
                const int key = 16*kk + v_key_off;
                const int ch  = 2*ntp + v_ch_off;
                uint32_t t[4];
                ldsm_x4_t(t, sV + (uint32_t)(key*128 + ((ch ^ (key & 7))*16)));
                mma_f16(of[2*ntp    ], pk[kk], &t[0], of[2*ntp    ]);
                mma_f16(of[2*ntp + 1], pk[kk], &t[2], of[2*ntp + 1]);
            }
        }
    }

    // epilogue: normalize, write ctx (fp16) [b][s][h*64+d]
    const int b = bh >> 4, h = bh & 15;
    const float inv0 = 1.0f / lc[0];
    const float inv1 = 1.0f / lc[2];
    const int qg0 = qbase + r;
    #pragma unroll
    for (int nt = 0; nt < 8; nt++) {
        const int d = nt*8 + c*2;
        *reinterpret_cast<uint32_t*>(
            g_ctx + ((size_t)(b*SS + qg0    ))*DD + h*HDIM + d) = f2h2(of[nt][0]*inv0, of[nt][1]*inv0);
        *reinterpret_cast<uint32_t*>(
            g_ctx + ((size_t)(b*SS + qg0 + 8))*DD + h*HDIM + d) = f2h2(of[nt][2]*inv1, of[nt][3]*inv1);
    }
}

// ---------------------------------------------------------------------------
// Launch
// ---------------------------------------------------------------------------
extern "C" void kernel_launch(void* const* d_in, const int* in_sizes, int n_in,
                              void* d_out, int out_size)
{
    const float* x  = (const float*)d_in[0];
    const float* Wq = (const float*)d_in[1];
    const float* Wk = (const float*)d_in[2];
    const float* Wv = (const float*)d_in[3];
    const float* Wo = (const float*)d_in[4];
    const float* bo = (const float*)d_in[5];
    float* out = (float*)d_out;

    (void)in_sizes; (void)n_in; (void)out_size;

    __half* dx;  cudaGetSymbolAddress((void**)&dx,  g_x16);
    __half* dwq; cudaGetSymbolAddress((void**)&dwq, g_wq16);
    __half* dwk; cudaGetSymbolAddress((void**)&dwk, g_wk16);
    __half* dwv; cudaGetSymbolAddress((void**)&dwv, g_wv16);
    __half* dwo; cudaGetSymbolAddress((void**)&dwo, g_wo16);

    const int nx4 = NTOK*DD/4;   // 1M
    const int nw4 = DD*DD/4;     // 256K
    cvt_x_kernel<<<nx4/256, 256>>>((const float4*)x, (uint2*)dx, nx4);
    cvt_w_kernel<<<dim3(nw4/256, 4), 256>>>(
        (const float4*)Wq, (const float4*)Wk, (const float4*)Wv, (const float4*)Wo,
        (uint2*)dwq, (uint2*)dwk, (uint2*)dwv, (uint2*)dwo);

    const int gsm = 4 * GSTG;   // 98304 bytes dynamic smem (4-stage pipeline)
    cudaFuncSetAttribute(qkv_gemm_kernel,
                         cudaFuncAttributeMaxDynamicSharedMemorySize, gsm);
    cudaFuncSetAttribute(oproj_kernel,
                         cudaFuncAttributeMaxDynamicSharedMemorySize, gsm);

    qkv_gemm_kernel<<<dim3(4, 32, 3), 256, gsm>>>();
    attn_kernel<<<dim3(16, 32), 256>>>();
    oproj_kernel<<<dim3(4, 32), 256, gsm>>>(bo, out);
}